// round 1
// baseline (speedup 1.0000x reference)
#include <cuda_runtime.h>
#include <math.h>

#define N_NODES 50000
#define E_EDGES 800000
#define N_ET    (E_EDGES + N_NODES)   // 850000 edges incl. self loops
#define EDIM    101
#define LP      104                   // padded loop_attr pitch (16B-aligned rows)
#define HC      128
#define NH      4

// ------------------------------ scratch ------------------------------------
__device__ int   g_is64;
__device__ int   g_eidx[2 * E_EDGES];
__device__ float g_loop[(size_t)N_NODES * LP];
__device__ float g_cnt [N_NODES];
__device__ float g_xl  [(size_t)N_NODES * HC];
__device__ float g_xr  [(size_t)N_NODES * HC];
__device__ float g_h   [(size_t)N_NODES * HC];
__device__ float g_t1  [(size_t)N_NODES * HC];
__device__ float g_logit[(size_t)N_ET * NH];
__device__ float g_amax[(size_t)N_NODES * NH];
__device__ float g_den [(size_t)N_NODES * NH];
__device__ float g_agg [(size_t)N_NODES * HC];

// ------------------------------ helpers ------------------------------------
__device__ __forceinline__ void redAdd4(float* p, float4 v) {
    asm volatile("red.global.add.v4.f32 [%0], {%1,%2,%3,%4};"
                 :: "l"(p), "f"(v.x), "f"(v.y), "f"(v.z), "f"(v.w) : "memory");
}

__device__ __forceinline__ void atomicMaxF(float* addr, float v) {
    if (v >= 0.f) atomicMax((int*)addr, __float_as_int(v));
    else          atomicMin((unsigned int*)addr, __float_as_uint(v));
}

// ------------------------------ index dtype hedge ---------------------------
__global__ void detect_idx(const void* ei) {
    const int* p = (const int*)ei;
    int all0 = 1;
    for (int i = 1; i < 64; i += 2) if (p[i] != 0) all0 = 0;
    g_is64 = all0;
}

__global__ void conv_idx(const void* ei) {
    int i = blockIdx.x * blockDim.x + threadIdx.x;
    if (i >= 2 * E_EDGES) return;
    int v;
    if (g_is64) v = (int)((const long long*)ei)[i];
    else        v = ((const int*)ei)[i];
    g_eidx[i] = v;
}

// ------------------------------ self-loop attr -----------------------------
__global__ void pre_init() {
    size_t i = (size_t)blockIdx.x * blockDim.x + threadIdx.x;
    if (i < (size_t)N_NODES * LP) g_loop[i] = 0.f;
    if (i < N_NODES) g_cnt[i] = 0.f;
}

__global__ void loop_accum(const int* __restrict__ dst, const float* __restrict__ ea) {
    int e = blockIdx.x * blockDim.x + threadIdx.x;
    if (e >= E_EDGES) return;
    int d = dst[e];
    float* out = g_loop + (size_t)d * LP;
    const float* a = ea + (size_t)e * EDIM;
#pragma unroll
    for (int k = 0; k < 100; k += 4) {
        float4 v = make_float4(a[k], a[k+1], a[k+2], a[k+3]);
        redAdd4(out + k, v);
    }
    atomicAdd(out + 100, a[100]);
    atomicAdd(&g_cnt[d], 1.0f);
}

__global__ void loop_fin() {
    size_t i = (size_t)blockIdx.x * blockDim.x + threadIdx.x;
    if (i >= (size_t)N_NODES * EDIM) return;
    int n = (int)(i / EDIM);
    int k = (int)(i - (size_t)n * EDIM);
    g_loop[(size_t)n * LP + k] *= 1.f / fmaxf(g_cnt[n], 1.f);
}

// ------------------------------ SGEMM (M x 128 = A[M,128] @ B[128,128]) ----
__global__ void sgemm128x128(const float* __restrict__ A, const float* __restrict__ B,
                             const float* __restrict__ bias, float* __restrict__ C,
                             int M, int relu) {
    __shared__ float As[8 * 132];
    __shared__ float Bs[8 * 128];
    int t = threadIdx.x;
    int m0 = blockIdx.x << 7;
    int la_m = t >> 1, la_k = (t & 1) << 2;
    int lb_k = t >> 5, lb_n = (t & 31) << 2;
    int tm = (t >> 4) << 3, tn = (t & 15) << 3;

    float acc[8][8];
#pragma unroll
    for (int i = 0; i < 8; i++)
#pragma unroll
        for (int j = 0; j < 8; j++) acc[i][j] = 0.f;

    for (int k0 = 0; k0 < 128; k0 += 8) {
        float4 av = make_float4(0.f, 0.f, 0.f, 0.f);
        if (m0 + la_m < M)
            av = *(const float4*)(A + (size_t)(m0 + la_m) * 128 + k0 + la_k);
        As[(la_k + 0) * 132 + la_m] = av.x;
        As[(la_k + 1) * 132 + la_m] = av.y;
        As[(la_k + 2) * 132 + la_m] = av.z;
        As[(la_k + 3) * 132 + la_m] = av.w;
        *(float4*)(Bs + lb_k * 128 + lb_n) =
            *(const float4*)(B + (size_t)(k0 + lb_k) * 128 + lb_n);
        __syncthreads();
#pragma unroll
        for (int k = 0; k < 8; k++) {
            float a[8], b[8];
            *(float4*)(a)     = *(const float4*)(As + k * 132 + tm);
            *(float4*)(a + 4) = *(const float4*)(As + k * 132 + tm + 4);
            *(float4*)(b)     = *(const float4*)(Bs + k * 128 + tn);
            *(float4*)(b + 4) = *(const float4*)(Bs + k * 128 + tn + 4);
#pragma unroll
            for (int i = 0; i < 8; i++)
#pragma unroll
                for (int j = 0; j < 8; j++) acc[i][j] += a[i] * b[j];
        }
        __syncthreads();
    }
#pragma unroll
    for (int i = 0; i < 8; i++) {
        int m = m0 + tm + i;
        if (m >= M) break;
        float o[8];
#pragma unroll
        for (int j = 0; j < 8; j++) {
            float v = acc[i][j] + bias[tn + j];
            o[j] = relu ? fmaxf(v, 0.f) : v;
        }
        *(float4*)(C + (size_t)m * 128 + tn)     = *(float4*)(o);
        *(float4*)(C + (size_t)m * 128 + tn + 4) = *(float4*)(o + 4);
    }
}

// ------------------------------ per-layer init ------------------------------
__global__ void layer_init() {
    size_t i = (size_t)blockIdx.x * blockDim.x + threadIdx.x;
    if (i < (size_t)N_NODES * HC) g_agg[i] = 0.f;
    if (i < (size_t)N_NODES * NH) {
        g_den[i] = 0.f;
        g_amax[i] = __int_as_float(0xff800000);  // -inf
    }
}

// ------------------ fused edge kernel: ee GEMM + gather + leaky + att dot ---
// block: 64 edges x 128 channels, 256 threads, each thread 4 edges x 8 ch
#define EL_SMEM_FLOATS (EDIM * 128 + EDIM * 68 + 128 + 256 + 128)
#define EL_SMEM_BYTES  (EL_SMEM_FLOATS * 4)

__global__ void edge_logit_kernel(const int* __restrict__ src, const int* __restrict__ dst,
                                  const float* __restrict__ eattr,
                                  const float* __restrict__ We, const float* __restrict__ att) {
    extern __shared__ float sm[];
    float* Ws   = sm;                     // [101][128]
    float* Ast  = sm + EDIM * 128;        // [101][68] transposed A tile
    float* attS = Ast + EDIM * 68;        // [4][32]
    float* slS  = attS + 128;             // [64][4] logit accumulators
    int*   ssS  = (int*)(slS + 256);      // [64]
    int*   dsS  = ssS + 64;               // [64]

    int t = threadIdx.x;
    size_t e0 = (size_t)blockIdx.x * 64;

    for (int i = t; i < EDIM * 128 / 4; i += 256)
        ((float4*)Ws)[i] = ((const float4*)We)[i];
    if (t < 128) attS[t] = att[t];
    slS[t] = 0.f;
    if (t < 64) {
        size_t e = e0 + t;
        int s = 0, d = 0;
        if (e < (size_t)N_ET) {
            if (e < E_EDGES) { s = src[e]; d = dst[e]; }
            else             { s = d = (int)(e - E_EDGES); }
        }
        ssS[t] = s; dsS[t] = d;
    }
    for (int i = t; i < 64 * EDIM; i += 256) {
        int le = i / EDIM, k = i - le * EDIM;
        size_t e = e0 + le;
        float v = 0.f;
        if (e < (size_t)N_ET)
            v = (e < E_EDGES) ? eattr[e * EDIM + k]
                              : g_loop[(e - E_EDGES) * (size_t)LP + k];
        Ast[k * 68 + le] = v;
    }
    __syncthreads();

    int tx = t & 15, ty = t >> 4;
    float acc[4][8];
#pragma unroll
    for (int i = 0; i < 4; i++)
#pragma unroll
        for (int j = 0; j < 8; j++) acc[i][j] = 0.f;

    const float* ap = Ast + (ty << 2);
    const float* bp = Ws + (tx << 3);
#pragma unroll 4
    for (int k = 0; k < EDIM; k++) {
        float4 a4 = *(const float4*)(ap + k * 68);
        float4 b0 = *(const float4*)(bp + k * 128);
        float4 b1 = *(const float4*)(bp + k * 128 + 4);
        float av[4] = {a4.x, a4.y, a4.z, a4.w};
        float bv[8] = {b0.x, b0.y, b0.z, b0.w, b1.x, b1.y, b1.z, b1.w};
#pragma unroll
        for (int i = 0; i < 4; i++)
#pragma unroll
            for (int j = 0; j < 8; j++) acc[i][j] += av[i] * bv[j];
    }

    int h = tx >> 2;
    int coff = (tx & 3) << 3;
#pragma unroll
    for (int i = 0; i < 4; i++) {
        int le = (ty << 2) + i;
        size_t e = e0 + le;
        if (e >= (size_t)N_ET) continue;
        int s = ssS[le], d = dsS[le];
        const float* xlp = g_xl + (size_t)s * HC + (tx << 3);
        const float* xrp = g_xr + (size_t)d * HC + (tx << 3);
        float4 l0 = *(const float4*)(xlp),     l1 = *(const float4*)(xlp + 4);
        float4 r0 = *(const float4*)(xrp),     r1 = *(const float4*)(xrp + 4);
        float lv[8] = {l0.x, l0.y, l0.z, l0.w, l1.x, l1.y, l1.z, l1.w};
        float rv[8] = {r0.x, r0.y, r0.z, r0.w, r1.x, r1.y, r1.z, r1.w};
        float part = 0.f;
#pragma unroll
        for (int j = 0; j < 8; j++) {
            float z = acc[i][j] + lv[j] + rv[j];
            z = (z > 0.f) ? z : 0.2f * z;      // leaky_relu, slope 0.2
            part += z * attS[h * 32 + coff + j];
        }
        atomicAdd(&slS[le * 4 + h], part);
    }
    __syncthreads();
    {
        int le = t >> 2, hh = t & 3;
        size_t e = e0 + le;
        if (e < (size_t)N_ET) g_logit[e * 4 + hh] = slS[t];
    }
}

// ------------------------------ segment max --------------------------------
__global__ void amax_kernel(const int* __restrict__ dst) {
    size_t i = (size_t)blockIdx.x * blockDim.x + threadIdx.x;
    if (i >= (size_t)N_ET * NH) return;
    size_t e = i >> 2;
    int h = (int)(i & 3);
    int d = (e < E_EDGES) ? dst[e] : (int)(e - E_EDGES);
    atomicMaxF(&g_amax[(size_t)d * NH + h], g_logit[i]);
}

// ---------------- unnormalized aggregation: agg[d] += e^x * xl[s] ----------
__global__ void edge_aggr(const int* __restrict__ src, const int* __restrict__ dst) {
    size_t gt = (size_t)blockIdx.x * blockDim.x + threadIdx.x;
    size_t e = gt >> 5;
    int lane = threadIdx.x & 31;
    if (e >= (size_t)N_ET) return;
    int s, d;
    if (e < E_EDGES) { s = src[e]; d = dst[e]; }
    else             { s = d = (int)(e - E_EDGES); }
    float ex = 0.f;
    if (lane < NH) {
        float lg = g_logit[e * NH + lane];
        ex = expf(lg - g_amax[(size_t)d * NH + lane]);
        atomicAdd(&g_den[(size_t)d * NH + lane], ex);
    }
    float exh = __shfl_sync(0xffffffffu, ex, lane >> 3);
    float4 xlv = *(const float4*)(g_xl + (size_t)s * HC + lane * 4);
    redAdd4(g_agg + (size_t)d * HC + lane * 4,
            make_float4(exh * xlv.x, exh * xlv.y, exh * xlv.z, exh * xlv.w));
}

// --------------------- h = relu(agg/(den+eps) + bias) ----------------------
__global__ void node_finalize(const float* __restrict__ bias, float* __restrict__ out) {
    size_t i = (size_t)blockIdx.x * blockDim.x + threadIdx.x;
    if (i >= (size_t)N_NODES * HC) return;
    int n = (int)(i >> 7), c = (int)(i & 127);
    float den = g_den[(size_t)n * NH + (c >> 5)];
    float v = g_agg[i] / (den + 1e-16f) + bias[c];
    out[i] = fmaxf(v, 0.f);
}

// --------------------- MLP tail: relu(t1@W2+b2) @ W3 + b3 ------------------
__global__ void mlp_tail(const float* __restrict__ W2, const float* __restrict__ b2,
                         const float* __restrict__ W3, const float* __restrict__ b3,
                         float* __restrict__ out) {
    __shared__ float W2s[128 * 64];
    __shared__ float t1s[16 * 132];
    __shared__ float W3s[64];
    int t = threadIdx.x;
    int n0 = blockIdx.x * 16;
    for (int i = t; i < 128 * 64 / 4; i += 128)
        ((float4*)W2s)[i] = ((const float4*)W2)[i];
    if (t < 64) W3s[t] = W3[t];
    for (int i = t; i < 16 * 128; i += 128) {
        int ln = i >> 7, k = i & 127;
        int n = n0 + ln;
        t1s[ln * 132 + k] = (n < N_NODES) ? g_t1[(size_t)n * 128 + k] : 0.f;
    }
    __syncthreads();
    int ln = t >> 3, jg = t & 7;
    float acc[8] = {0.f, 0.f, 0.f, 0.f, 0.f, 0.f, 0.f, 0.f};
#pragma unroll 4
    for (int k = 0; k < 128; k++) {
        float a = t1s[ln * 132 + k];
        float4 w0 = *(const float4*)(W2s + k * 64 + jg * 8);
        float4 w1 = *(const float4*)(W2s + k * 64 + jg * 8 + 4);
        acc[0] += a * w0.x; acc[1] += a * w0.y; acc[2] += a * w0.z; acc[3] += a * w0.w;
        acc[4] += a * w1.x; acc[5] += a * w1.y; acc[6] += a * w1.z; acc[7] += a * w1.w;
    }
    float part = 0.f;
#pragma unroll
    for (int j = 0; j < 8; j++) {
        float t2 = fmaxf(acc[j] + b2[jg * 8 + j], 0.f);
        part += t2 * W3s[jg * 8 + j];
    }
    part += __shfl_down_sync(0xffffffffu, part, 4, 8);
    part += __shfl_down_sync(0xffffffffu, part, 2, 8);
    part += __shfl_down_sync(0xffffffffu, part, 1, 8);
    int n = n0 + ln;
    if (jg == 0 && n < N_NODES) out[n] = part + b3[0];
}

// ------------------------------ launch -------------------------------------
extern "C" void kernel_launch(void* const* d_in, const int* in_sizes, int n_in,
                              void* d_out, int out_size) {
    const float* x       = (const float*)d_in[0];
    const void*  ei_raw  = d_in[1];
    const float* ea      = (const float*)d_in[2];
    const float* c1_Wl   = (const float*)d_in[3];
    const float* c1_bl   = (const float*)d_in[4];
    const float* c1_Wr   = (const float*)d_in[5];
    const float* c1_br   = (const float*)d_in[6];
    const float* c1_We   = (const float*)d_in[7];
    const float* c1_att  = (const float*)d_in[8];
    const float* c1_bias = (const float*)d_in[9];
    const float* c2_Wl   = (const float*)d_in[10];
    const float* c2_bl   = (const float*)d_in[11];
    const float* c2_Wr   = (const float*)d_in[12];
    const float* c2_br   = (const float*)d_in[13];
    const float* c2_We   = (const float*)d_in[14];
    const float* c2_att  = (const float*)d_in[15];
    const float* c2_bias = (const float*)d_in[16];
    const float* W1      = (const float*)d_in[17];
    const float* b1      = (const float*)d_in[18];
    const float* W2      = (const float*)d_in[19];
    const float* b2      = (const float*)d_in[20];
    const float* W3      = (const float*)d_in[21];
    const float* b3      = (const float*)d_in[22];
    float* out = (float*)d_out;

    float *p_xl, *p_xr, *p_h, *p_t1;
    int *p_eidx;
    cudaGetSymbolAddress((void**)&p_xl, g_xl);
    cudaGetSymbolAddress((void**)&p_xr, g_xr);
    cudaGetSymbolAddress((void**)&p_h, g_h);
    cudaGetSymbolAddress((void**)&p_t1, g_t1);
    cudaGetSymbolAddress((void**)&p_eidx, g_eidx);
    const int* src = p_eidx;
    const int* dst = p_eidx + E_EDGES;

    cudaFuncSetAttribute(edge_logit_kernel,
                         cudaFuncAttributeMaxDynamicSharedMemorySize, EL_SMEM_BYTES);

    const int T = 256;
    int gemm_blocks = (N_NODES + 127) / 128;
    int el_blocks = (N_ET + 63) / 64;
    int nhc_blocks = ((size_t)N_NODES * HC + T - 1) / T;

    detect_idx<<<1, 1>>>(ei_raw);
    conv_idx<<<(2 * E_EDGES + T - 1) / T, T>>>(ei_raw);

    pre_init<<<((size_t)N_NODES * LP + T - 1) / T, T>>>();
    loop_accum<<<(E_EDGES + T - 1) / T, T>>>(dst, ea);
    loop_fin<<<((size_t)N_NODES * EDIM + T - 1) / T, T>>>();

    // ---- layer 1 ----
    sgemm128x128<<<gemm_blocks, T>>>(x, c1_Wl, c1_bl, p_xl, N_NODES, 0);
    sgemm128x128<<<gemm_blocks, T>>>(x, c1_Wr, c1_br, p_xr, N_NODES, 0);
    layer_init<<<nhc_blocks, T>>>();
    edge_logit_kernel<<<el_blocks, T, EL_SMEM_BYTES>>>(src, dst, ea, c1_We, c1_att);
    amax_kernel<<<((size_t)N_ET * NH + T - 1) / T, T>>>(dst);
    edge_aggr<<<((size_t)N_ET * 32 + T - 1) / T, T>>>(src, dst);
    node_finalize<<<nhc_blocks, T>>>(c1_bias, p_h);

    // ---- layer 2 ----
    sgemm128x128<<<gemm_blocks, T>>>(p_h, c2_Wl, c2_bl, p_xl, N_NODES, 0);
    sgemm128x128<<<gemm_blocks, T>>>(p_h, c2_Wr, c2_br, p_xr, N_NODES, 0);
    layer_init<<<nhc_blocks, T>>>();
    edge_logit_kernel<<<el_blocks, T, EL_SMEM_BYTES>>>(src, dst, ea, c2_We, c2_att);
    amax_kernel<<<((size_t)N_ET * NH + T - 1) / T, T>>>(dst);
    edge_aggr<<<((size_t)N_ET * 32 + T - 1) / T, T>>>(src, dst);
    node_finalize<<<nhc_blocks, T>>>(c2_bias, p_h);

    // ---- MLP head ----
    sgemm128x128<<<gemm_blocks, T>>>(p_h, W1, b1, p_t1, N_NODES, 1);
    mlp_tail<<<(N_NODES + 15) / 16, 128>>>(W2, b2, W3, b3, out);
}

// round 3
// speedup vs baseline: 1.0604x; 1.0604x over previous
#include <cuda_runtime.h>
#include <math.h>

#define N_NODES 50000
#define E_EDGES 800000
#define N_ET    (E_EDGES + N_NODES)   // 850000 edges incl. self loops
#define EDIM    101
#define LP      104                   // padded loop_attr pitch
#define HC      128
#define NH      4

// edge-kernel tiling
#define TILE_E  256
#define KC      16
#define KPAD    112                   // 7 chunks of 16
#define APITCH  264                   // TILE_E + 8
#define NTILES  ((N_ET + TILE_E - 1) / TILE_E)

// ------------------------------ scratch ------------------------------------
__device__ int   g_is64;
__device__ int   g_eidx[2 * E_EDGES];
__device__ float g_loop[(size_t)N_NODES * LP];
__device__ float g_cnt [N_NODES];
__device__ float g_xl  [(size_t)N_NODES * HC];
__device__ float g_xr  [(size_t)N_NODES * HC];
__device__ float g_h   [(size_t)N_NODES * HC];
__device__ float g_t1  [(size_t)N_NODES * HC];
__device__ float g_logit[(size_t)N_ET * NH];
__device__ float g_amax[(size_t)N_NODES * NH];
__device__ float g_den [(size_t)N_NODES * NH];
__device__ float g_agg [(size_t)N_NODES * HC];

// ------------------------------ helpers ------------------------------------
__device__ __forceinline__ void redAdd4(float* p, float4 v) {
    asm volatile("red.global.add.v4.f32 [%0], {%1,%2,%3,%4};"
                 :: "l"(p), "f"(v.x), "f"(v.y), "f"(v.z), "f"(v.w) : "memory");
}

__device__ __forceinline__ void atomicMaxF(float* addr, float v) {
    if (v >= 0.f) atomicMax((int*)addr, __float_as_int(v));
    else          atomicMin((unsigned int*)addr, __float_as_uint(v));
}

// packed fp32x2 math (Blackwell FFMA2)
__device__ __forceinline__ void fma2(unsigned long long& d,
                                     unsigned long long a, unsigned long long b) {
    asm("fma.rn.f32x2 %0, %1, %2, %0;" : "+l"(d) : "l"(a), "l"(b));
}
__device__ __forceinline__ unsigned long long dup2(float x) {
    unsigned long long r;
    asm("mov.b64 %0, {%1, %1};" : "=l"(r) : "r"(__float_as_uint(x)));
    return r;
}
__device__ __forceinline__ float2 unpk2(unsigned long long v) {
    unsigned int lo, hi;
    asm("mov.b64 {%0, %1}, %2;" : "=r"(lo), "=r"(hi) : "l"(v));
    return make_float2(__uint_as_float(lo), __uint_as_float(hi));
}

// ------------------------------ index dtype hedge ---------------------------
__global__ void detect_idx(const void* ei) {
    const int* p = (const int*)ei;
    int all0 = 1;
    for (int i = 1; i < 64; i += 2) if (p[i] != 0) all0 = 0;
    g_is64 = all0;
}

__global__ void conv_idx(const void* ei) {
    int i = blockIdx.x * blockDim.x + threadIdx.x;
    if (i >= 2 * E_EDGES) return;
    int v;
    if (g_is64) v = (int)((const long long*)ei)[i];
    else        v = ((const int*)ei)[i];
    g_eidx[i] = v;
}

// ------------------------------ self-loop attr -----------------------------
__global__ void pre_init() {
    size_t i = (size_t)blockIdx.x * blockDim.x + threadIdx.x;
    if (i < (size_t)N_NODES * LP) g_loop[i] = 0.f;
    if (i < N_NODES) g_cnt[i] = 0.f;
}

__global__ void loop_accum(const int* __restrict__ dst, const float* __restrict__ ea) {
    int e = blockIdx.x * blockDim.x + threadIdx.x;
    if (e >= E_EDGES) return;
    int d = dst[e];
    float* out = g_loop + (size_t)d * LP;
    const float* a = ea + (size_t)e * EDIM;
#pragma unroll
    for (int k = 0; k < 100; k += 4) {
        float4 v = make_float4(a[k], a[k+1], a[k+2], a[k+3]);
        redAdd4(out + k, v);
    }
    atomicAdd(out + 100, a[100]);
    atomicAdd(&g_cnt[d], 1.0f);
}

__global__ void loop_fin() {
    size_t i = (size_t)blockIdx.x * blockDim.x + threadIdx.x;
    if (i >= (size_t)N_NODES * EDIM) return;
    int n = (int)(i / EDIM);
    int k = (int)(i - (size_t)n * EDIM);
    g_loop[(size_t)n * LP + k] *= 1.f / fmaxf(g_cnt[n], 1.f);
}

// ------------------------------ SGEMM (M x 128 = A[M,128] @ B[128,128]) ----
__global__ void sgemm128x128(const float* __restrict__ A, const float* __restrict__ B,
                             const float* __restrict__ bias, float* __restrict__ C,
                             int M, int relu) {
    __shared__ float As[8 * 132];
    __shared__ float Bs[8 * 128];
    int t = threadIdx.x;
    int m0 = blockIdx.x << 7;
    int la_m = t >> 1, la_k = (t & 1) << 2;
    int lb_k = t >> 5, lb_n = (t & 31) << 2;
    int tm = (t >> 4) << 3, tn = (t & 15) << 3;

    unsigned long long acc[8][4];
#pragma unroll
    for (int i = 0; i < 8; i++)
#pragma unroll
        for (int j = 0; j < 4; j++) acc[i][j] = 0ull;

    for (int k0 = 0; k0 < 128; k0 += 8) {
        float4 av = make_float4(0.f, 0.f, 0.f, 0.f);
        if (m0 + la_m < M)
            av = *(const float4*)(A + (size_t)(m0 + la_m) * 128 + k0 + la_k);
        As[(la_k + 0) * 132 + la_m] = av.x;
        As[(la_k + 1) * 132 + la_m] = av.y;
        As[(la_k + 2) * 132 + la_m] = av.z;
        As[(la_k + 3) * 132 + la_m] = av.w;
        *(float4*)(Bs + lb_k * 128 + lb_n) =
            *(const float4*)(B + (size_t)(k0 + lb_k) * 128 + lb_n);
        __syncthreads();
#pragma unroll
        for (int k = 0; k < 8; k++) {
            float a[8];
            *(float4*)(a)     = *(const float4*)(As + k * 132 + tm);
            *(float4*)(a + 4) = *(const float4*)(As + k * 132 + tm + 4);
            ulonglong2 bA = *(const ulonglong2*)(Bs + k * 128 + tn);
            ulonglong2 bB = *(const ulonglong2*)(Bs + k * 128 + tn + 4);
            unsigned long long bp[4] = {bA.x, bA.y, bB.x, bB.y};
#pragma unroll
            for (int i = 0; i < 8; i++) {
                unsigned long long ad = dup2(a[i]);
#pragma unroll
                for (int j = 0; j < 4; j++) fma2(acc[i][j], ad, bp[j]);
            }
        }
        __syncthreads();
    }
#pragma unroll
    for (int i = 0; i < 8; i++) {
        int m = m0 + tm + i;
        if (m >= M) break;
        float o[8];
#pragma unroll
        for (int j = 0; j < 4; j++) {
            float2 p = unpk2(acc[i][j]);
            float v0 = p.x + bias[tn + 2*j];
            float v1 = p.y + bias[tn + 2*j + 1];
            o[2*j]   = relu ? fmaxf(v0, 0.f) : v0;
            o[2*j+1] = relu ? fmaxf(v1, 0.f) : v1;
        }
        *(float4*)(C + (size_t)m * 128 + tn)     = *(float4*)(o);
        *(float4*)(C + (size_t)m * 128 + tn + 4) = *(float4*)(o + 4);
    }
}

// ------------------------------ per-layer init ------------------------------
__global__ void layer_init() {
    size_t i = (size_t)blockIdx.x * blockDim.x + threadIdx.x;
    if (i < (size_t)N_NODES * HC) g_agg[i] = 0.f;
    if (i < (size_t)N_NODES * NH) {
        g_den[i] = 0.f;
        g_amax[i] = __int_as_float(0xff800000);  // -inf
    }
}

// ------------- persistent fused edge kernel (f32x2 GEMM + logit + amax) -----
// smem: Bs[112][128] + As[2][16][264] + att[128] + ssS/dsS[256 each]
#define EL_SMEM_BYTES (KPAD*128*4 + 2*KC*APITCH*4 + 128*4 + 2*TILE_E*4)

__global__ __launch_bounds__(256, 1)
void edge_logit_fused(const int* __restrict__ src, const int* __restrict__ dst,
                      const float* __restrict__ eattr,
                      const float* __restrict__ We, const float* __restrict__ att) {
    extern __shared__ float sm[];
    float* Bs   = sm;                           // [112][128]
    float* As   = Bs + KPAD * 128;              // [2][16][264]
    float* attS = As + 2 * KC * APITCH;         // [128]
    int*   ssS  = (int*)(attS + 128);           // [256]
    int*   dsS  = ssS + TILE_E;                 // [256]

    int t = threadIdx.x;
    int cg = t & 7;          // channel group (16 ch)
    int eg = t >> 3;         // edge group (8 edges)
    int head = cg >> 1;

    // load We once (pad k >= 101 with zeros)
    for (int i = t; i < KPAD * 128; i += 256)
        Bs[i] = (i < EDIM * 128) ? We[i] : 0.f;
    if (t < 128) attS[t] = att[t];
    __syncthreads();

    for (int tile = blockIdx.x; tile < NTILES; tile += gridDim.x) {
        size_t e0 = (size_t)tile * TILE_E;

        // edge indices for this tile
        {
            size_t e = e0 + t;
            int s = 0, d = 0;
            if (e < (size_t)N_ET) {
                if (e < E_EDGES) { s = src[e]; d = dst[e]; }
                else             { s = d = (int)(e - E_EDGES); }
            }
            ssS[t] = s; dsS[t] = d;
        }

        // prefetch chunk 0 (thread t owns edge row t: 16 consecutive k's)
        float pf[KC];
        {
            size_t e = e0 + t;
            const float* bp = (e < E_EDGES) ? (eattr + e * EDIM)
                                            : (g_loop + (e - E_EDGES) * (size_t)LP);
            bool ok = (e < (size_t)N_ET);
#pragma unroll
            for (int i = 0; i < KC; i++) pf[i] = ok ? bp[i] : 0.f;
        }
        __syncthreads();               // prev tile done, indices visible
#pragma unroll
        for (int i = 0; i < KC; i++) As[i * APITCH + t] = pf[i];
        __syncthreads();

        unsigned long long acc[8][8];
#pragma unroll
        for (int i = 0; i < 8; i++)
#pragma unroll
            for (int j = 0; j < 8; j++) acc[i][j] = 0ull;

#pragma unroll 1
        for (int c = 0; c < 7; c++) {
            // prefetch next chunk into regs
            if (c < 6) {
                size_t e = e0 + t;
                int k0 = (c + 1) * KC;
                const float* bp = (e < E_EDGES) ? (eattr + e * EDIM)
                                                : (g_loop + (e - E_EDGES) * (size_t)LP);
                bool ok = (e < (size_t)N_ET);
#pragma unroll
                for (int i = 0; i < KC; i++) {
                    int k = k0 + i;
                    pf[i] = (ok && k < EDIM) ? bp[k] : 0.f;
                }
            }
            const float* Ab = As + (c & 1) * (KC * APITCH);
            const float* Bb = Bs + c * KC * 128;
#pragma unroll
            for (int k = 0; k < KC; k++) {
                float4 a0 = *(const float4*)(Ab + k * APITCH + (eg << 3));
                float4 a1 = *(const float4*)(Ab + k * APITCH + (eg << 3) + 4);
                ulonglong2 bA = *(const ulonglong2*)(Bb + (k << 7) + (cg << 4));
                ulonglong2 bB = *(const ulonglong2*)(Bb + (k << 7) + (cg << 4) + 4);
                ulonglong2 bC = *(const ulonglong2*)(Bb + (k << 7) + (cg << 4) + 8);
                ulonglong2 bD = *(const ulonglong2*)(Bb + (k << 7) + (cg << 4) + 12);
                unsigned long long bp8[8] = {bA.x, bA.y, bB.x, bB.y,
                                             bC.x, bC.y, bD.x, bD.y};
                float av[8] = {a0.x, a0.y, a0.z, a0.w, a1.x, a1.y, a1.z, a1.w};
#pragma unroll
                for (int i = 0; i < 8; i++) {
                    unsigned long long ad = dup2(av[i]);
#pragma unroll
                    for (int j = 0; j < 8; j++) fma2(acc[i][j], ad, bp8[j]);
                }
            }
            if (c < 6) {
                __syncthreads();
                float* Aw = As + ((c + 1) & 1) * (KC * APITCH);
#pragma unroll
                for (int i = 0; i < KC; i++) Aw[i * APITCH + t] = pf[i];
                __syncthreads();
            }
        }

        // epilogue: gather xl/xr, leaky_relu, att-dot, pair-reduce, logit+amax
        // NOTE: no early exit — every lane executes the shuffle (fixes R2 hang);
        // invalid edges use index 0 (safe to read) and are predicated at the store.
        const float* ats = attS + (head << 5) + ((cg & 1) << 4);
#pragma unroll 1
        for (int i = 0; i < 8; i++) {
            int el = (eg << 3) + i;
            size_t e = e0 + el;
            bool valid = (e < (size_t)N_ET);
            int s = valid ? ssS[el] : 0;
            int d = valid ? dsS[el] : 0;
            const float* xlp = g_xl + (size_t)s * HC + (cg << 4);
            const float* xrp = g_xr + (size_t)d * HC + (cg << 4);
            float lv[16], rv[16];
#pragma unroll
            for (int q = 0; q < 4; q++) {
                *(float4*)(lv + 4*q) = *(const float4*)(xlp + 4*q);
                *(float4*)(rv + 4*q) = *(const float4*)(xrp + 4*q);
            }
            float part = 0.f;
#pragma unroll
            for (int j = 0; j < 8; j++) {
                float2 p = unpk2(acc[i][j]);
                float z0 = p.x + lv[2*j]     + rv[2*j];
                float z1 = p.y + lv[2*j + 1] + rv[2*j + 1];
                z0 = (z0 > 0.f) ? z0 : 0.2f * z0;
                z1 = (z1 > 0.f) ? z1 : 0.2f * z1;
                part += z0 * ats[2*j] + z1 * ats[2*j + 1];
            }
            part += __shfl_xor_sync(0xffffffffu, part, 1);
            if (valid && (cg & 1) == 0) {
                g_logit[e * NH + head] = part;
                atomicMaxF(&g_amax[(size_t)d * NH + head], part);
            }
        }
        __syncthreads();   // protect ssS/As before next tile
    }
}

// ---------------- unnormalized aggregation: agg[d] += e^x * xl[s] ----------
__global__ void edge_aggr(const int* __restrict__ src, const int* __restrict__ dst) {
    size_t gt = (size_t)blockIdx.x * blockDim.x + threadIdx.x;
    size_t e = gt >> 5;
    int lane = threadIdx.x & 31;
    if (e >= (size_t)N_ET) return;
    int s, d;
    if (e < E_EDGES) { s = src[e]; d = dst[e]; }
    else             { s = d = (int)(e - E_EDGES); }
    float ex = 0.f;
    if (lane < NH) {
        float lg = g_logit[e * NH + lane];
        ex = expf(lg - g_amax[(size_t)d * NH + lane]);
        atomicAdd(&g_den[(size_t)d * NH + lane], ex);
    }
    float exh = __shfl_sync(0xffffffffu, ex, lane >> 3);
    float4 xlv = *(const float4*)(g_xl + (size_t)s * HC + lane * 4);
    redAdd4(g_agg + (size_t)d * HC + lane * 4,
            make_float4(exh * xlv.x, exh * xlv.y, exh * xlv.z, exh * xlv.w));
}

// --------------------- h = relu(agg/(den+eps) + bias) ----------------------
__global__ void node_finalize(const float* __restrict__ bias, float* __restrict__ out) {
    size_t i = (size_t)blockIdx.x * blockDim.x + threadIdx.x;
    if (i >= (size_t)N_NODES * HC) return;
    int n = (int)(i >> 7), c = (int)(i & 127);
    float den = g_den[(size_t)n * NH + (c >> 5)];
    float v = g_agg[i] / (den + 1e-16f) + bias[c];
    out[i] = fmaxf(v, 0.f);
}

// --------------------- MLP tail: relu(t1@W2+b2) @ W3 + b3 ------------------
__global__ void mlp_tail(const float* __restrict__ W2, const float* __restrict__ b2,
                         const float* __restrict__ W3, const float* __restrict__ b3,
                         float* __restrict__ out) {
    __shared__ float W2s[128 * 64];
    __shared__ float t1s[16 * 132];
    __shared__ float W3s[64];
    int t = threadIdx.x;
    int n0 = blockIdx.x * 16;
    for (int i = t; i < 128 * 64 / 4; i += 128)
        ((float4*)W2s)[i] = ((const float4*)W2)[i];
    if (t < 64) W3s[t] = W3[t];
    for (int i = t; i < 16 * 128; i += 128) {
        int ln = i >> 7, k = i & 127;
        int n = n0 + ln;
        t1s[ln * 132 + k] = (n < N_NODES) ? g_t1[(size_t)n * 128 + k] : 0.f;
    }
    __syncthreads();
    int ln = t >> 3, jg = t & 7;
    float acc[8] = {0.f, 0.f, 0.f, 0.f, 0.f, 0.f, 0.f, 0.f};
#pragma unroll 4
    for (int k = 0; k < 128; k++) {
        float a = t1s[ln * 132 + k];
        float4 w0 = *(const float4*)(W2s + k * 64 + jg * 8);
        float4 w1 = *(const float4*)(W2s + k * 64 + jg * 8 + 4);
        acc[0] += a * w0.x; acc[1] += a * w0.y; acc[2] += a * w0.z; acc[3] += a * w0.w;
        acc[4] += a * w1.x; acc[5] += a * w1.y; acc[6] += a * w1.z; acc[7] += a * w1.w;
    }
    float part = 0.f;
#pragma unroll
    for (int j = 0; j < 8; j++) {
        float t2 = fmaxf(acc[j] + b2[jg * 8 + j], 0.f);
        part += t2 * W3s[jg * 8 + j];
    }
    part += __shfl_down_sync(0xffffffffu, part, 4, 8);
    part += __shfl_down_sync(0xffffffffu, part, 2, 8);
    part += __shfl_down_sync(0xffffffffu, part, 1, 8);
    int n = n0 + ln;
    if (jg == 0 && n < N_NODES) out[n] = part + b3[0];
}

// ------------------------------ launch -------------------------------------
extern "C" void kernel_launch(void* const* d_in, const int* in_sizes, int n_in,
                              void* d_out, int out_size) {
    const float* x       = (const float*)d_in[0];
    const void*  ei_raw  = d_in[1];
    const float* ea      = (const float*)d_in[2];
    const float* c1_Wl   = (const float*)d_in[3];
    const float* c1_bl   = (const float*)d_in[4];
    const float* c1_Wr   = (const float*)d_in[5];
    const float* c1_br   = (const float*)d_in[6];
    const float* c1_We   = (const float*)d_in[7];
    const float* c1_att  = (const float*)d_in[8];
    const float* c1_bias = (const float*)d_in[9];
    const float* c2_Wl   = (const float*)d_in[10];
    const float* c2_bl   = (const float*)d_in[11];
    const float* c2_Wr   = (const float*)d_in[12];
    const float* c2_br   = (const float*)d_in[13];
    const float* c2_We   = (const float*)d_in[14];
    const float* c2_att  = (const float*)d_in[15];
    const float* c2_bias = (const float*)d_in[16];
    const float* W1      = (const float*)d_in[17];
    const float* b1      = (const float*)d_in[18];
    const float* W2      = (const float*)d_in[19];
    const float* b2      = (const float*)d_in[20];
    const float* W3      = (const float*)d_in[21];
    const float* b3      = (const float*)d_in[22];
    float* out = (float*)d_out;

    float *p_xl, *p_xr, *p_h, *p_t1;
    int *p_eidx;
    cudaGetSymbolAddress((void**)&p_xl, g_xl);
    cudaGetSymbolAddress((void**)&p_xr, g_xr);
    cudaGetSymbolAddress((void**)&p_h, g_h);
    cudaGetSymbolAddress((void**)&p_t1, g_t1);
    cudaGetSymbolAddress((void**)&p_eidx, g_eidx);
    const int* src = p_eidx;
    const int* dst = p_eidx + E_EDGES;

    cudaFuncSetAttribute(edge_logit_fused,
                         cudaFuncAttributeMaxDynamicSharedMemorySize, EL_SMEM_BYTES);

    int nsm = 148;
    cudaDeviceGetAttribute(&nsm, cudaDevAttrMultiProcessorCount, 0);

    const int T = 256;
    int gemm_blocks = (N_NODES + 127) / 128;
    int nhc_blocks = ((size_t)N_NODES * HC + T - 1) / T;

    detect_idx<<<1, 1>>>(ei_raw);
    conv_idx<<<(2 * E_EDGES + T - 1) / T, T>>>(ei_raw);

    pre_init<<<((size_t)N_NODES * LP + T - 1) / T, T>>>();
    loop_accum<<<(E_EDGES + T - 1) / T, T>>>(dst, ea);
    loop_fin<<<((size_t)N_NODES * EDIM + T - 1) / T, T>>>();

    // ---- layer 1 ----
    sgemm128x128<<<gemm_blocks, T>>>(x, c1_Wl, c1_bl, p_xl, N_NODES, 0);
    sgemm128x128<<<gemm_blocks, T>>>(x, c1_Wr, c1_br, p_xr, N_NODES, 0);
    layer_init<<<nhc_blocks, T>>>();
    edge_logit_fused<<<nsm, T, EL_SMEM_BYTES>>>(src, dst, ea, c1_We, c1_att);
    edge_aggr<<<((size_t)N_ET * 32 + T - 1) / T, T>>>(src, dst);
    node_finalize<<<nhc_blocks, T>>>(c1_bias, p_h);

    // ---- layer 2 ----
    sgemm128x128<<<gemm_blocks, T>>>(p_h, c2_Wl, c2_bl, p_xl, N_NODES, 0);
    sgemm128x128<<<gemm_blocks, T>>>(p_h, c2_Wr, c2_br, p_xr, N_NODES, 0);
    layer_init<<<nhc_blocks, T>>>();
    edge_logit_fused<<<nsm, T, EL_SMEM_BYTES>>>(src, dst, ea, c2_We, c2_att);
    edge_aggr<<<((size_t)N_ET * 32 + T - 1) / T, T>>>(src, dst);
    node_finalize<<<nhc_blocks, T>>>(c2_bias, p_h);

    // ---- MLP head ----
    sgemm128x128<<<gemm_blocks, T>>>(p_h, W1, b1, p_t1, N_NODES, 1);
    mlp_tail<<<(N_NODES + 15) / 16, 128>>>(W2, b2, W3, b3, out);
}

// round 4
// speedup vs baseline: 1.4189x; 1.3381x over previous
#include <cuda_runtime.h>
#include <math.h>

#define N_NODES 50000
#define E_EDGES 800000
#define N_ET    (E_EDGES + N_NODES)   // 850000 edges incl. self loops
#define EDIM    101
#define LP      104                   // padded loop_attr pitch
#define HC      128
#define NH      4

// edge-kernel tiling
#define TILE_E  256
#define KC      16
#define KPAD    112                   // 7 chunks of 16
#define ATP     264                   // A^T pitch (TILE_E + 8)
#define NTILES  ((N_ET + TILE_E - 1) / TILE_E)

// ------------------------------ scratch ------------------------------------
__device__ int   g_is64;
__device__ int   g_eidx[2 * E_EDGES];
__device__ float g_loop[(size_t)N_NODES * LP];
__device__ float g_cnt [N_NODES];
__device__ float g_xl  [(size_t)N_NODES * HC];
__device__ float g_xr  [(size_t)N_NODES * HC];
__device__ float g_h   [(size_t)N_NODES * HC];
__device__ float g_t1  [(size_t)N_NODES * HC];
__device__ float g_den [(size_t)N_NODES * NH];
__device__ float g_agg [(size_t)N_NODES * HC];

// ------------------------------ helpers ------------------------------------
__device__ __forceinline__ void redAdd4(float* p, float4 v) {
    asm volatile("red.global.add.v4.f32 [%0], {%1,%2,%3,%4};"
                 :: "l"(p), "f"(v.x), "f"(v.y), "f"(v.z), "f"(v.w) : "memory");
}

// packed fp32x2 math (Blackwell FFMA2)
__device__ __forceinline__ void fma2(unsigned long long& d,
                                     unsigned long long a, unsigned long long b) {
    asm("fma.rn.f32x2 %0, %1, %2, %0;" : "+l"(d) : "l"(a), "l"(b));
}
__device__ __forceinline__ unsigned long long dup2(float x) {
    unsigned long long r;
    asm("mov.b64 %0, {%1, %1};" : "=l"(r) : "r"(__float_as_uint(x)));
    return r;
}
__device__ __forceinline__ float2 unpk2(unsigned long long v) {
    unsigned int lo, hi;
    asm("mov.b64 {%0, %1}, %2;" : "=r"(lo), "=r"(hi) : "l"(v));
    return make_float2(__uint_as_float(lo), __uint_as_float(hi));
}

// ------------------------------ index dtype hedge ---------------------------
__global__ void detect_idx(const void* ei) {
    const int* p = (const int*)ei;
    int all0 = 1;
    for (int i = 1; i < 64; i += 2) if (p[i] != 0) all0 = 0;
    g_is64 = all0;
}

__global__ void conv_idx(const void* ei) {
    int i = blockIdx.x * blockDim.x + threadIdx.x;
    if (i >= 2 * E_EDGES) return;
    int v;
    if (g_is64) v = (int)((const long long*)ei)[i];
    else        v = ((const int*)ei)[i];
    g_eidx[i] = v;
}

// ------------------------------ self-loop attr -----------------------------
__global__ void pre_init() {
    size_t i = (size_t)blockIdx.x * blockDim.x + threadIdx.x;
    if (i < (size_t)N_NODES * LP) g_loop[i] = 0.f;
    if (i < N_NODES) g_cnt[i] = 0.f;
}

__global__ void loop_accum(const int* __restrict__ dst, const float* __restrict__ ea) {
    int e = blockIdx.x * blockDim.x + threadIdx.x;
    if (e >= E_EDGES) return;
    int d = dst[e];
    float* out = g_loop + (size_t)d * LP;
    const float* a = ea + (size_t)e * EDIM;
#pragma unroll
    for (int k = 0; k < 100; k += 4) {
        float4 v = make_float4(a[k], a[k+1], a[k+2], a[k+3]);
        redAdd4(out + k, v);
    }
    atomicAdd(out + 100, a[100]);
    atomicAdd(&g_cnt[d], 1.0f);
}

__global__ void loop_fin() {
    size_t i = (size_t)blockIdx.x * blockDim.x + threadIdx.x;
    if (i >= (size_t)N_NODES * EDIM) return;
    int n = (int)(i / EDIM);
    int k = (int)(i - (size_t)n * EDIM);
    g_loop[(size_t)n * LP + k] *= 1.f / fmaxf(g_cnt[n], 1.f);
}

// ------------------------------ SGEMM (M x 128 = A[M,128] @ B[128,128]) ----
// B fragment mapping (t&15)*4 and +64 -> max 2-way smem conflicts.
__global__ void sgemm128x128(const float* __restrict__ A, const float* __restrict__ B,
                             const float* __restrict__ bias, float* __restrict__ C,
                             int M, int relu) {
    __shared__ float As[8 * 132];
    __shared__ float Bs[8 * 128];
    int t = threadIdx.x;
    int m0 = blockIdx.x << 7;
    int la_m = t >> 1, la_k = (t & 1) << 2;
    int lb_k = t >> 5, lb_n = (t & 31) << 2;
    int tm = (t >> 4) << 3;
    int tn = (t & 15) << 2;            // cols tn..tn+3 and tn+64..tn+67

    unsigned long long acc[8][4];
#pragma unroll
    for (int i = 0; i < 8; i++)
#pragma unroll
        for (int j = 0; j < 4; j++) acc[i][j] = 0ull;

    for (int k0 = 0; k0 < 128; k0 += 8) {
        float4 av = make_float4(0.f, 0.f, 0.f, 0.f);
        if (m0 + la_m < M)
            av = *(const float4*)(A + (size_t)(m0 + la_m) * 128 + k0 + la_k);
        As[(la_k + 0) * 132 + la_m] = av.x;
        As[(la_k + 1) * 132 + la_m] = av.y;
        As[(la_k + 2) * 132 + la_m] = av.z;
        As[(la_k + 3) * 132 + la_m] = av.w;
        *(float4*)(Bs + lb_k * 128 + lb_n) =
            *(const float4*)(B + (size_t)(k0 + lb_k) * 128 + lb_n);
        __syncthreads();
#pragma unroll
        for (int k = 0; k < 8; k++) {
            float a[8];
            *(float4*)(a)     = *(const float4*)(As + k * 132 + tm);
            *(float4*)(a + 4) = *(const float4*)(As + k * 132 + tm + 4);
            ulonglong2 bA = *(const ulonglong2*)(Bs + k * 128 + tn);
            ulonglong2 bB = *(const ulonglong2*)(Bs + k * 128 + tn + 64);
            unsigned long long bp[4] = {bA.x, bA.y, bB.x, bB.y};
#pragma unroll
            for (int i = 0; i < 8; i++) {
                unsigned long long ad = dup2(a[i]);
#pragma unroll
                for (int j = 0; j < 4; j++) fma2(acc[i][j], ad, bp[j]);
            }
        }
        __syncthreads();
    }
#pragma unroll
    for (int i = 0; i < 8; i++) {
        int m = m0 + tm + i;
        if (m >= M) break;
        float o0[4], o1[4];
        float2 p0 = unpk2(acc[i][0]), p1 = unpk2(acc[i][1]);
        float2 p2 = unpk2(acc[i][2]), p3 = unpk2(acc[i][3]);
        o0[0] = p0.x + bias[tn + 0];  o0[1] = p0.y + bias[tn + 1];
        o0[2] = p1.x + bias[tn + 2];  o0[3] = p1.y + bias[tn + 3];
        o1[0] = p2.x + bias[tn + 64]; o1[1] = p2.y + bias[tn + 65];
        o1[2] = p3.x + bias[tn + 66]; o1[3] = p3.y + bias[tn + 67];
        if (relu) {
#pragma unroll
            for (int j = 0; j < 4; j++) {
                o0[j] = fmaxf(o0[j], 0.f);
                o1[j] = fmaxf(o1[j], 0.f);
            }
        }
        *(float4*)(C + (size_t)m * 128 + tn)      = *(float4*)(o0);
        *(float4*)(C + (size_t)m * 128 + tn + 64) = *(float4*)(o1);
    }
}

// ------------------------------ per-layer init ------------------------------
__global__ void layer_init() {
    size_t i = (size_t)blockIdx.x * blockDim.x + threadIdx.x;
    if (i < (size_t)N_NODES * HC) g_agg[i] = 0.f;
    if (i < (size_t)N_NODES * NH) g_den[i] = 0.f;
}

// ---- persistent fully-fused edge kernel: ee GEMM + logit + exp + aggregate -
// 512 threads: warp w owns 16 edges, lane owns channels lane*4..lane*4+3.
// B reads: lane*16B -> 512B/warp contiguous, conflict-free.
// A reads: warp-uniform broadcast.
#define EL_SMEM_FLOATS (KPAD*128 + 2*KC*ATP + 128)
#define EL_SMEM_BYTES  (EL_SMEM_FLOATS*4 + 2*TILE_E*4)

__global__ __launch_bounds__(512, 1)
void edge_fused(const int* __restrict__ src, const int* __restrict__ dst,
                const float* __restrict__ eattr,
                const float* __restrict__ We, const float* __restrict__ att) {
    extern __shared__ float sm[];
    float* Bs   = sm;                       // [112][128]
    float* As   = Bs + KPAD * 128;          // [2][16][ATP]  (A^T: [k][edge])
    float* attS = As + 2 * KC * ATP;        // [128]
    int*   ssS  = (int*)(attS + 128);       // [256]
    int*   dsS  = ssS + TILE_E;             // [256]

    int t = threadIdx.x;
    int lane = t & 31;
    int w = t >> 5;                         // warp 0..15
    int head = lane >> 3;

    // load We once (zero-pad k >= 101)
    for (int i = t; i < KPAD * 128; i += 512)
        Bs[i] = (i < EDIM * 128) ? We[i] : 0.f;
    if (t < 128) attS[t] = att[t];

    int pe = t >> 1;                        // edge slot this thread stages
    int kh = (t & 1) * 8;                   // k-half within chunk

    for (int tile = blockIdx.x; tile < NTILES; tile += gridDim.x) {
        size_t e0 = (size_t)tile * TILE_E;
        __syncthreads();                    // prev tile fully done / Bs ready

        if (t < TILE_E) {
            size_t e = e0 + t;
            int s = 0, d = 0;
            if (e < (size_t)N_ET) {
                if (e < E_EDGES) { s = src[e]; d = dst[e]; }
                else             { s = d = (int)(e - E_EDGES); }
            }
            ssS[t] = s; dsS[t] = d;
        }

        // stage chunk 0 of A^T
        float pf[8];
        {
            size_t e = e0 + pe;
            bool ok = (e < (size_t)N_ET);
            const float* bp = (e < E_EDGES) ? (eattr + e * EDIM)
                            : (g_loop + (ok ? (e - E_EDGES) : 0) * (size_t)LP);
#pragma unroll
            for (int i = 0; i < 8; i++) pf[i] = ok ? bp[kh + i] : 0.f;
        }
#pragma unroll
        for (int i = 0; i < 8; i++) As[(kh + i) * ATP + pe] = pf[i];
        __syncthreads();

        unsigned long long acc[16][2];
#pragma unroll
        for (int i = 0; i < 16; i++) { acc[i][0] = 0ull; acc[i][1] = 0ull; }

#pragma unroll 1
        for (int c = 0; c < 7; c++) {
            if (c < 6) {
                size_t e = e0 + pe;
                bool ok = (e < (size_t)N_ET);
                const float* bp = (e < E_EDGES) ? (eattr + e * EDIM)
                                : (g_loop + (ok ? (e - E_EDGES) : 0) * (size_t)LP);
                int k0 = (c + 1) * KC + kh;
#pragma unroll
                for (int i = 0; i < 8; i++) {
                    int k = k0 + i;
                    pf[i] = (ok && k < EDIM) ? bp[k] : 0.f;
                }
            }
            const float* Ab = As + (c & 1) * (KC * ATP) + (w << 4);
            const float* Bb = Bs + c * KC * 128 + (lane << 2);
#pragma unroll
            for (int k = 0; k < KC; k++) {
                ulonglong2 bv = *(const ulonglong2*)(Bb + (k << 7));
                float a[16];
#pragma unroll
                for (int q = 0; q < 4; q++)
                    *(float4*)(a + 4*q) = *(const float4*)(Ab + k * ATP + 4*q);
#pragma unroll
                for (int i = 0; i < 16; i++) {
                    unsigned long long ad = dup2(a[i]);
                    fma2(acc[i][0], ad, bv.x);
                    fma2(acc[i][1], ad, bv.y);
                }
            }
            if (c < 6) {
                __syncthreads();
                float* Aw = As + ((c + 1) & 1) * (KC * ATP);
#pragma unroll
                for (int i = 0; i < 8; i++) Aw[(kh + i) * ATP + pe] = pf[i];
                __syncthreads();
            }
        }

        // epilogue: z = ee + xl[s] + xr[d]; leaky; logit per head; exp; aggregate.
        // all lanes run shuffles unconditionally; validity only gates stores.
        float4 av = *(const float4*)(attS + (lane << 2));
#pragma unroll 1
        for (int i = 0; i < 16; i++) {
            int el = (w << 4) + i;
            size_t e = e0 + el;
            bool valid = (e < (size_t)N_ET);
            int s = valid ? ssS[el] : 0;
            int d = valid ? dsS[el] : 0;
            float4 xlv = *(const float4*)(g_xl + (size_t)s * HC + (lane << 2));
            float4 xrv = *(const float4*)(g_xr + (size_t)d * HC + (lane << 2));
            float2 p0 = unpk2(acc[i][0]), p1 = unpk2(acc[i][1]);
            float z0 = p0.x + xlv.x + xrv.x;
            float z1 = p0.y + xlv.y + xrv.y;
            float z2 = p1.x + xlv.z + xrv.z;
            float z3 = p1.y + xlv.w + xrv.w;
            z0 = (z0 > 0.f) ? z0 : 0.2f * z0;
            z1 = (z1 > 0.f) ? z1 : 0.2f * z1;
            z2 = (z2 > 0.f) ? z2 : 0.2f * z2;
            z3 = (z3 > 0.f) ? z3 : 0.2f * z3;
            float part = z0 * av.x + z1 * av.y + z2 * av.z + z3 * av.w;
            part += __shfl_xor_sync(0xffffffffu, part, 1);
            part += __shfl_xor_sync(0xffffffffu, part, 2);
            part += __shfl_xor_sync(0xffffffffu, part, 4);
            // lanes 8h..8h+7 now hold logit of head h for this edge
            float ex = __expf(part);
            if (valid) {
                if ((lane & 7) == 0)
                    atomicAdd(&g_den[(size_t)d * NH + head], ex);
                redAdd4(g_agg + (size_t)d * HC + (lane << 2),
                        make_float4(ex * xlv.x, ex * xlv.y, ex * xlv.z, ex * xlv.w));
            }
        }
    }
}

// --------------------- h = relu(agg/(den+eps) + bias) ----------------------
__global__ void node_finalize(const float* __restrict__ bias, float* __restrict__ out) {
    size_t i = (size_t)blockIdx.x * blockDim.x + threadIdx.x;
    if (i >= (size_t)N_NODES * HC) return;
    int n = (int)(i >> 7), c = (int)(i & 127);
    float den = g_den[(size_t)n * NH + (c >> 5)];
    float v = g_agg[i] / (den + 1e-16f) + bias[c];
    out[i] = fmaxf(v, 0.f);
}

// --------------------- MLP tail: relu(t1@W2+b2) @ W3 + b3 ------------------
__global__ void mlp_tail(const float* __restrict__ W2, const float* __restrict__ b2,
                         const float* __restrict__ W3, const float* __restrict__ b3,
                         float* __restrict__ out) {
    __shared__ float W2s[128 * 64];
    __shared__ float t1s[16 * 132];
    __shared__ float W3s[64];
    int t = threadIdx.x;
    int n0 = blockIdx.x * 16;
    for (int i = t; i < 128 * 64 / 4; i += 128)
        ((float4*)W2s)[i] = ((const float4*)W2)[i];
    if (t < 64) W3s[t] = W3[t];
    for (int i = t; i < 16 * 128; i += 128) {
        int ln = i >> 7, k = i & 127;
        int n = n0 + ln;
        t1s[ln * 132 + k] = (n < N_NODES) ? g_t1[(size_t)n * 128 + k] : 0.f;
    }
    __syncthreads();
    int ln = t >> 3, jg = t & 7;
    float acc[8] = {0.f, 0.f, 0.f, 0.f, 0.f, 0.f, 0.f, 0.f};
#pragma unroll 4
    for (int k = 0; k < 128; k++) {
        float a = t1s[ln * 132 + k];
        float4 w0 = *(const float4*)(W2s + k * 64 + jg * 8);
        float4 w1 = *(const float4*)(W2s + k * 64 + jg * 8 + 4);
        acc[0] += a * w0.x; acc[1] += a * w0.y; acc[2] += a * w0.z; acc[3] += a * w0.w;
        acc[4] += a * w1.x; acc[5] += a * w1.y; acc[6] += a * w1.z; acc[7] += a * w1.w;
    }
    float part = 0.f;
#pragma unroll
    for (int j = 0; j < 8; j++) {
        float t2 = fmaxf(acc[j] + b2[jg * 8 + j], 0.f);
        part += t2 * W3s[jg * 8 + j];
    }
    part += __shfl_down_sync(0xffffffffu, part, 4, 8);
    part += __shfl_down_sync(0xffffffffu, part, 2, 8);
    part += __shfl_down_sync(0xffffffffu, part, 1, 8);
    int n = n0 + ln;
    if (jg == 0 && n < N_NODES) out[n] = part + b3[0];
}

// ------------------------------ launch -------------------------------------
extern "C" void kernel_launch(void* const* d_in, const int* in_sizes, int n_in,
                              void* d_out, int out_size) {
    const float* x       = (const float*)d_in[0];
    const void*  ei_raw  = d_in[1];
    const float* ea      = (const float*)d_in[2];
    const float* c1_Wl   = (const float*)d_in[3];
    const float* c1_bl   = (const float*)d_in[4];
    const float* c1_Wr   = (const float*)d_in[5];
    const float* c1_br   = (const float*)d_in[6];
    const float* c1_We   = (const float*)d_in[7];
    const float* c1_att  = (const float*)d_in[8];
    const float* c1_bias = (const float*)d_in[9];
    const float* c2_Wl   = (const float*)d_in[10];
    const float* c2_bl   = (const float*)d_in[11];
    const float* c2_Wr   = (const float*)d_in[12];
    const float* c2_br   = (const float*)d_in[13];
    const float* c2_We   = (const float*)d_in[14];
    const float* c2_att  = (const float*)d_in[15];
    const float* c2_bias = (const float*)d_in[16];
    const float* W1      = (const float*)d_in[17];
    const float* b1      = (const float*)d_in[18];
    const float* W2      = (const float*)d_in[19];
    const float* b2      = (const float*)d_in[20];
    const float* W3      = (const float*)d_in[21];
    const float* b3      = (const float*)d_in[22];
    float* out = (float*)d_out;

    float *p_xl, *p_xr, *p_h, *p_t1;
    int *p_eidx;
    cudaGetSymbolAddress((void**)&p_xl, g_xl);
    cudaGetSymbolAddress((void**)&p_xr, g_xr);
    cudaGetSymbolAddress((void**)&p_h, g_h);
    cudaGetSymbolAddress((void**)&p_t1, g_t1);
    cudaGetSymbolAddress((void**)&p_eidx, g_eidx);
    const int* src = p_eidx;
    const int* dst = p_eidx + E_EDGES;

    cudaFuncSetAttribute(edge_fused,
                         cudaFuncAttributeMaxDynamicSharedMemorySize, EL_SMEM_BYTES);

    int nsm = 148;
    cudaDeviceGetAttribute(&nsm, cudaDevAttrMultiProcessorCount, 0);

    const int T = 256;
    int gemm_blocks = (N_NODES + 127) / 128;
    int nhc_blocks = ((size_t)N_NODES * HC + T - 1) / T;

    detect_idx<<<1, 1>>>(ei_raw);
    conv_idx<<<(2 * E_EDGES + T - 1) / T, T>>>(ei_raw);

    pre_init<<<((size_t)N_NODES * LP + T - 1) / T, T>>>();
    loop_accum<<<(E_EDGES + T - 1) / T, T>>>(dst, ea);
    loop_fin<<<((size_t)N_NODES * EDIM + T - 1) / T, T>>>();

    // ---- layer 1 ----
    sgemm128x128<<<gemm_blocks, T>>>(x, c1_Wl, c1_bl, p_xl, N_NODES, 0);
    sgemm128x128<<<gemm_blocks, T>>>(x, c1_Wr, c1_br, p_xr, N_NODES, 0);
    layer_init<<<nhc_blocks, T>>>();
    edge_fused<<<nsm, 512, EL_SMEM_BYTES>>>(src, dst, ea, c1_We, c1_att);
    node_finalize<<<nhc_blocks, T>>>(c1_bias, p_h);

    // ---- layer 2 ----
    sgemm128x128<<<gemm_blocks, T>>>(p_h, c2_Wl, c2_bl, p_xl, N_NODES, 0);
    sgemm128x128<<<gemm_blocks, T>>>(p_h, c2_Wr, c2_br, p_xr, N_NODES, 0);
    layer_init<<<nhc_blocks, T>>>();
    edge_fused<<<nsm, 512, EL_SMEM_BYTES>>>(src, dst, ea, c2_We, c2_att);
    node_finalize<<<nhc_blocks, T>>>(c2_bias, p_h);

    // ---- MLP head ----
    sgemm128x128<<<gemm_blocks, T>>>(p_h, W1, b1, p_t1, N_NODES, 1);
    mlp_tail<<<(N_NODES + 15) / 16, 128>>>(W2, b2, W3, b3, out);
}

// round 6
// speedup vs baseline: 1.4422x; 1.0164x over previous
#include <cuda_runtime.h>
#include <math.h>

#define N_NODES 50000
#define E_EDGES 800000
#define N_ET    (E_EDGES + N_NODES)   // 850000 edges incl. self loops
#define EDIM    101
#define LP      104                   // padded loop_attr pitch
#define HC      128
#define NH      4

// edge-kernel tiling
#define TILE_E  256
#define KC      16
#define KPAD    112                   // 7 chunks of 16
#define ATP     264                   // A^T pitch (TILE_E + 8)
#define NTILES  ((N_ET + TILE_E - 1) / TILE_E)

// ------------------------------ scratch ------------------------------------
__device__ int   g_is64;
__device__ int   g_eidx[2 * E_EDGES];
__device__ float g_loop[(size_t)N_NODES * LP];
__device__ float g_cnt [N_NODES];
__device__ float g_xl  [(size_t)N_NODES * HC];
__device__ float g_xr  [(size_t)N_NODES * HC];
__device__ float g_h   [(size_t)N_NODES * HC];
__device__ float g_t1  [(size_t)N_NODES * HC];
__device__ float g_den [(size_t)N_NODES * NH];
__device__ float g_agg [(size_t)N_NODES * HC];

// ------------------------------ helpers ------------------------------------
__device__ __forceinline__ void redAdd4(float* p, float4 v) {
    asm volatile("red.global.add.v4.f32 [%0], {%1,%2,%3,%4};"
                 :: "l"(p), "f"(v.x), "f"(v.y), "f"(v.z), "f"(v.w) : "memory");
}

// packed fp32x2 math (Blackwell FFMA2)
__device__ __forceinline__ void fma2(unsigned long long& d,
                                     unsigned long long a, unsigned long long b) {
    asm("fma.rn.f32x2 %0, %1, %2, %0;" : "+l"(d) : "l"(a), "l"(b));
}
__device__ __forceinline__ unsigned long long dup2(float x) {
    unsigned long long r;
    asm("mov.b64 %0, {%1, %1};" : "=l"(r) : "r"(__float_as_uint(x)));
    return r;
}
__device__ __forceinline__ float2 unpk2(unsigned long long v) {
    unsigned int lo, hi;
    asm("mov.b64 {%0, %1}, %2;" : "=r"(lo), "=r"(hi) : "l"(v));
    return make_float2(__uint_as_float(lo), __uint_as_float(hi));
}

// ------------------------------ index dtype hedge ---------------------------
__global__ void detect_idx(const void* ei) {
    const int* p = (const int*)ei;
    int all0 = 1;
    for (int i = 1; i < 64; i += 2) if (p[i] != 0) all0 = 0;
    g_is64 = all0;
}

__global__ void conv_idx(const void* ei) {
    int i = blockIdx.x * blockDim.x + threadIdx.x;
    if (i >= 2 * E_EDGES) return;
    int v;
    if (g_is64) v = (int)((const long long*)ei)[i];
    else        v = ((const int*)ei)[i];
    g_eidx[i] = v;
}

// ------------------------------ self-loop attr -----------------------------
__global__ void pre_init() {
    size_t i = (size_t)blockIdx.x * blockDim.x + threadIdx.x;
    if (i < (size_t)N_NODES * LP) g_loop[i] = 0.f;
    if (i < N_NODES) g_cnt[i] = 0.f;
}

__global__ void loop_accum(const int* __restrict__ dst, const float* __restrict__ ea) {
    int e = blockIdx.x * blockDim.x + threadIdx.x;
    if (e >= E_EDGES) return;
    int d = dst[e];
    float* out = g_loop + (size_t)d * LP;
    const float* a = ea + (size_t)e * EDIM;
#pragma unroll
    for (int k = 0; k < 100; k += 4) {
        float4 v = make_float4(a[k], a[k+1], a[k+2], a[k+3]);
        redAdd4(out + k, v);
    }
    atomicAdd(out + 100, a[100]);
    atomicAdd(&g_cnt[d], 1.0f);
}

__global__ void loop_fin() {
    size_t i = (size_t)blockIdx.x * blockDim.x + threadIdx.x;
    if (i >= (size_t)N_NODES * EDIM) return;
    int n = (int)(i / EDIM);
    int k = (int)(i - (size_t)n * EDIM);
    g_loop[(size_t)n * LP + k] *= 1.f / fmaxf(g_cnt[n], 1.f);
}

// ------------------------------ SGEMM (M x 128 = A[M,128] @ B[128,128]) ----
__global__ void sgemm128x128(const float* __restrict__ A, const float* __restrict__ B,
                             const float* __restrict__ bias, float* __restrict__ C,
                             int M, int relu) {
    __shared__ float As[8 * 132];
    __shared__ float Bs[8 * 128];
    int t = threadIdx.x;
    int m0 = blockIdx.x << 7;
    int la_m = t >> 1, la_k = (t & 1) << 2;
    int lb_k = t >> 5, lb_n = (t & 31) << 2;
    int tm = (t >> 4) << 3;
    int tn = (t & 15) << 2;

    unsigned long long acc[8][4];
#pragma unroll
    for (int i = 0; i < 8; i++)
#pragma unroll
        for (int j = 0; j < 4; j++) acc[i][j] = 0ull;

    for (int k0 = 0; k0 < 128; k0 += 8) {
        float4 av = make_float4(0.f, 0.f, 0.f, 0.f);
        if (m0 + la_m < M)
            av = *(const float4*)(A + (size_t)(m0 + la_m) * 128 + k0 + la_k);
        As[(la_k + 0) * 132 + la_m] = av.x;
        As[(la_k + 1) * 132 + la_m] = av.y;
        As[(la_k + 2) * 132 + la_m] = av.z;
        As[(la_k + 3) * 132 + la_m] = av.w;
        *(float4*)(Bs + lb_k * 128 + lb_n) =
            *(const float4*)(B + (size_t)(k0 + lb_k) * 128 + lb_n);
        __syncthreads();
#pragma unroll
        for (int k = 0; k < 8; k++) {
            float a[8];
            *(float4*)(a)     = *(const float4*)(As + k * 132 + tm);
            *(float4*)(a + 4) = *(const float4*)(As + k * 132 + tm + 4);
            ulonglong2 bA = *(const ulonglong2*)(Bs + k * 128 + tn);
            ulonglong2 bB = *(const ulonglong2*)(Bs + k * 128 + tn + 64);
            unsigned long long bp[4] = {bA.x, bA.y, bB.x, bB.y};
#pragma unroll
            for (int i = 0; i < 8; i++) {
                unsigned long long ad = dup2(a[i]);
#pragma unroll
                for (int j = 0; j < 4; j++) fma2(acc[i][j], ad, bp[j]);
            }
        }
        __syncthreads();
    }
#pragma unroll
    for (int i = 0; i < 8; i++) {
        int m = m0 + tm + i;
        if (m >= M) break;
        float o0[4], o1[4];
        float2 p0 = unpk2(acc[i][0]), p1 = unpk2(acc[i][1]);
        float2 p2 = unpk2(acc[i][2]), p3 = unpk2(acc[i][3]);
        o0[0] = p0.x + bias[tn + 0];  o0[1] = p0.y + bias[tn + 1];
        o0[2] = p1.x + bias[tn + 2];  o0[3] = p1.y + bias[tn + 3];
        o1[0] = p2.x + bias[tn + 64]; o1[1] = p2.y + bias[tn + 65];
        o1[2] = p3.x + bias[tn + 66]; o1[3] = p3.y + bias[tn + 67];
        if (relu) {
#pragma unroll
            for (int j = 0; j < 4; j++) {
                o0[j] = fmaxf(o0[j], 0.f);
                o1[j] = fmaxf(o1[j], 0.f);
            }
        }
        *(float4*)(C + (size_t)m * 128 + tn)      = *(float4*)(o0);
        *(float4*)(C + (size_t)m * 128 + tn + 64) = *(float4*)(o1);
    }
}

// ------------------------------ per-layer init ------------------------------
__global__ void layer_init() {
    size_t i = (size_t)blockIdx.x * blockDim.x + threadIdx.x;
    if (i < (size_t)N_NODES * HC) g_agg[i] = 0.f;
    if (i < (size_t)N_NODES * NH) g_den[i] = 0.f;
}

// ---- persistent fully-fused edge kernel: ee GEMM + logit + exp + aggregate -
// 512 threads: warp w owns 16 edges (= 8 packed pairs), lane owns channels
// lane*4..lane*4+3.  a-operand: ulonglong direct from A^T (edge pairs,
// warp-uniform broadcast).  b-operand: 4 dup2/k (was 16 -> alu pipe freed).
#define EL_SMEM_FLOATS (KPAD*128 + 2*KC*ATP + 128)
#define EL_SMEM_BYTES  (EL_SMEM_FLOATS*4 + 2*TILE_E*4)

__global__ __launch_bounds__(512, 1)
void edge_fused(const int* __restrict__ src, const int* __restrict__ dst,
                const float* __restrict__ eattr,
                const float* __restrict__ We, const float* __restrict__ att) {
    extern __shared__ float sm[];
    float* Bs   = sm;                       // [112][128]
    float* As   = Bs + KPAD * 128;          // [2][16][ATP]  (A^T: [k][edge])
    float* attS = As + 2 * KC * ATP;        // [128]
    int*   ssS  = (int*)(attS + 128);       // [256]
    int*   dsS  = ssS + TILE_E;             // [256]

    int t = threadIdx.x;
    int lane = t & 31;
    int w = t >> 5;                         // warp 0..15
    int head = lane >> 3;

    // load We once (zero-pad k >= 101)
    for (int i = t; i < KPAD * 128; i += 512)
        Bs[i] = (i < EDIM * 128) ? We[i] : 0.f;
    if (t < 128) attS[t] = att[t];

    int pe = t >> 1;                        // edge slot this thread stages
    int kh = (t & 1) * 8;                   // k-half within chunk

    for (int tile = blockIdx.x; tile < NTILES; tile += gridDim.x) {
        size_t e0 = (size_t)tile * TILE_E;
        __syncthreads();                    // prev tile fully done / Bs ready

        if (t < TILE_E) {
            size_t e = e0 + t;
            int s = 0, d = 0;
            if (e < (size_t)N_ET) {
                if (e < E_EDGES) { s = src[e]; d = dst[e]; }
                else             { s = d = (int)(e - E_EDGES); }
            }
            ssS[t] = s; dsS[t] = d;
        }

        // stage chunk 0 of A^T
        float pf[8];
        {
            size_t e = e0 + pe;
            bool ok = (e < (size_t)N_ET);
            const float* bp = (e < E_EDGES) ? (eattr + e * EDIM)
                            : (g_loop + (ok ? (e - E_EDGES) : 0) * (size_t)LP);
#pragma unroll
            for (int i = 0; i < 8; i++) pf[i] = ok ? bp[kh + i] : 0.f;
        }
#pragma unroll
        for (int i = 0; i < 8; i++) As[(kh + i) * ATP + pe] = pf[i];
        __syncthreads();

        // acc[pair][channel], pair = edges (2p, 2p+1) packed in f32x2
        unsigned long long acc[8][4];
#pragma unroll
        for (int p = 0; p < 8; p++)
#pragma unroll
            for (int c = 0; c < 4; c++) acc[p][c] = 0ull;

#pragma unroll 1
        for (int c = 0; c < 7; c++) {
            if (c < 6) {
                size_t e = e0 + pe;
                bool ok = (e < (size_t)N_ET);
                const float* bp = (e < E_EDGES) ? (eattr + e * EDIM)
                                : (g_loop + (ok ? (e - E_EDGES) : 0) * (size_t)LP);
                int k0 = (c + 1) * KC + kh;
#pragma unroll
                for (int i = 0; i < 8; i++) {
                    int k = k0 + i;
                    pf[i] = (ok && k < EDIM) ? bp[k] : 0.f;
                }
            }
            const float* Ab = As + (c & 1) * (KC * ATP) + (w << 4);
            const float* Bb = Bs + c * KC * 128 + (lane << 2);
#pragma unroll
            for (int k = 0; k < KC; k++) {
                // A: 8 edge-pairs (16 floats) as 4 x 16B warp-uniform loads
                ulonglong2 a01 = *(const ulonglong2*)(Ab + k * ATP);
                ulonglong2 a23 = *(const ulonglong2*)(Ab + k * ATP + 4);
                ulonglong2 a45 = *(const ulonglong2*)(Ab + k * ATP + 8);
                ulonglong2 a67 = *(const ulonglong2*)(Ab + k * ATP + 12);
                unsigned long long ap[8] = {a01.x, a01.y, a23.x, a23.y,
                                            a45.x, a45.y, a67.x, a67.y};
                // B: lane's 4 channels, duplicated (4 dup2 per k)
                float4 b4 = *(const float4*)(Bb + (k << 7));
                unsigned long long bd[4] = {dup2(b4.x), dup2(b4.y),
                                            dup2(b4.z), dup2(b4.w)};
#pragma unroll
                for (int p = 0; p < 8; p++)
#pragma unroll
                    for (int cc = 0; cc < 4; cc++) fma2(acc[p][cc], ap[p], bd[cc]);
            }
            if (c < 6) {
                __syncthreads();
                float* Aw = As + ((c + 1) & 1) * (KC * ATP);
#pragma unroll
                for (int i = 0; i < 8; i++) Aw[(kh + i) * ATP + pe] = pf[i];
                __syncthreads();
            }
        }

        // epilogue: z = ee + xl[s] + xr[d]; leaky; head logit; exp; aggregate.
        // all lanes run shuffles unconditionally; validity only gates stores.
        float4 av = *(const float4*)(attS + (lane << 2));
#pragma unroll 1
        for (int p = 0; p < 8; p++) {
            float2 c0 = unpk2(acc[p][0]);
            float2 c1 = unpk2(acc[p][1]);
            float2 c2 = unpk2(acc[p][2]);
            float2 c3 = unpk2(acc[p][3]);
#pragma unroll
            for (int i = 0; i < 2; i++) {
                int el = (w << 4) + (p << 1) + i;
                size_t e = e0 + el;
                bool valid = (e < (size_t)N_ET);
                int s = valid ? ssS[el] : 0;
                int d = valid ? dsS[el] : 0;
                float4 xlv = *(const float4*)(g_xl + (size_t)s * HC + (lane << 2));
                float4 xrv = *(const float4*)(g_xr + (size_t)d * HC + (lane << 2));
                float e0v = i ? c0.y : c0.x;
                float e1v = i ? c1.y : c1.x;
                float e2v = i ? c2.y : c2.x;
                float e3v = i ? c3.y : c3.x;
                float z0 = e0v + xlv.x + xrv.x;
                float z1 = e1v + xlv.y + xrv.y;
                float z2 = e2v + xlv.z + xrv.z;
                float z3 = e3v + xlv.w + xrv.w;
                z0 = (z0 > 0.f) ? z0 : 0.2f * z0;
                z1 = (z1 > 0.f) ? z1 : 0.2f * z1;
                z2 = (z2 > 0.f) ? z2 : 0.2f * z2;
                z3 = (z3 > 0.f) ? z3 : 0.2f * z3;
                float part = z0 * av.x + z1 * av.y + z2 * av.z + z3 * av.w;
                part += __shfl_xor_sync(0xffffffffu, part, 1);
                part += __shfl_xor_sync(0xffffffffu, part, 2);
                part += __shfl_xor_sync(0xffffffffu, part, 4);
                float ex = __expf(part);
                if (valid) {
                    if ((lane & 7) == 0)
                        atomicAdd(&g_den[(size_t)d * NH + head], ex);
                    redAdd4(g_agg + (size_t)d * HC + (lane << 2),
                            make_float4(ex * xlv.x, ex * xlv.y,
                                        ex * xlv.z, ex * xlv.w));
                }
            }
        }
    }
}

// --------------------- h = relu(agg/(den+eps) + bias) ----------------------
__global__ void node_finalize(const float* __restrict__ bias, float* __restrict__ out) {
    size_t i = (size_t)blockIdx.x * blockDim.x + threadIdx.x;
    if (i >= (size_t)N_NODES * HC) return;
    int n = (int)(i >> 7), c = (int)(i & 127);
    float den = g_den[(size_t)n * NH + (c >> 5)];
    float v = g_agg[i] / (den + 1e-16f) + bias[c];
    out[i] = fmaxf(v, 0.f);
}

// --------------------- MLP tail: relu(t1@W2+b2) @ W3 + b3 ------------------
__global__ void mlp_tail(const float* __restrict__ W2, const float* __restrict__ b2,
                         const float* __restrict__ W3, const float* __restrict__ b3,
                         float* __restrict__ out) {
    __shared__ float W2s[128 * 64];
    __shared__ float t1s[16 * 132];
    __shared__ float W3s[64];
    int t = threadIdx.x;
    int n0 = blockIdx.x * 16;
    for (int i = t; i < 128 * 64 / 4; i += 128)
        ((float4*)W2s)[i] = ((const float4*)W2)[i];
    if (t < 64) W3s[t] = W3[t];
    for (int i = t; i < 16 * 128; i += 128) {
        int ln = i >> 7, k = i & 127;
        int n = n0 + ln;
        t1s[ln * 132 + k] = (n < N_NODES) ? g_t1[(size_t)n * 128 + k] : 0.f;
    }
    __syncthreads();
    int ln = t >> 3, jg = t & 7;
    float acc[8] = {0.f, 0.f, 0.f, 0.f, 0.f, 0.f, 0.f, 0.f};
#pragma unroll 4
    for (int k = 0; k < 128; k++) {
        float a = t1s[ln * 132 + k];
        float4 w0 = *(const float4*)(W2s + k * 64 + jg * 8);
        float4 w1 = *(const float4*)(W2s + k * 64 + jg * 8 + 4);
        acc[0] += a * w0.x; acc[1] += a * w0.y; acc[2] += a * w0.z; acc[3] += a * w0.w;
        acc[4] += a * w1.x; acc[5] += a * w1.y; acc[6] += a * w1.z; acc[7] += a * w1.w;
    }
    float part = 0.f;
#pragma unroll
    for (int j = 0; j < 8; j++) {
        float t2 = fmaxf(acc[j] + b2[jg * 8 + j], 0.f);
        part += t2 * W3s[jg * 8 + j];
    }
    part += __shfl_down_sync(0xffffffffu, part, 4, 8);
    part += __shfl_down_sync(0xffffffffu, part, 2, 8);
    part += __shfl_down_sync(0xffffffffu, part, 1, 8);
    int n = n0 + ln;
    if (jg == 0 && n < N_NODES) out[n] = part + b3[0];
}

// ------------------------------ launch -------------------------------------
extern "C" void kernel_launch(void* const* d_in, const int* in_sizes, int n_in,
                              void* d_out, int out_size) {
    const float* x       = (const float*)d_in[0];
    const void*  ei_raw  = d_in[1];
    const float* ea      = (const float*)d_in[2];
    const float* c1_Wl   = (const float*)d_in[3];
    const float* c1_bl   = (const float*)d_in[4];
    const float* c1_Wr   = (const float*)d_in[5];
    const float* c1_br   = (const float*)d_in[6];
    const float* c1_We   = (const float*)d_in[7];
    const float* c1_att  = (const float*)d_in[8];
    const float* c1_bias = (const float*)d_in[9];
    const float* c2_Wl   = (const float*)d_in[10];
    const float* c2_bl   = (const float*)d_in[11];
    const float* c2_Wr   = (const float*)d_in[12];
    const float* c2_br   = (const float*)d_in[13];
    const float* c2_We   = (const float*)d_in[14];
    const float* c2_att  = (const float*)d_in[15];
    const float* c2_bias = (const float*)d_in[16];
    const float* W1      = (const float*)d_in[17];
    const float* b1      = (const float*)d_in[18];
    const float* W2      = (const float*)d_in[19];
    const float* b2      = (const float*)d_in[20];
    const float* W3      = (const float*)d_in[21];
    const float* b3      = (const float*)d_in[22];
    float* out = (float*)d_out;

    float *p_xl, *p_xr, *p_h, *p_t1;
    int *p_eidx;
    cudaGetSymbolAddress((void**)&p_xl, g_xl);
    cudaGetSymbolAddress((void**)&p_xr, g_xr);
    cudaGetSymbolAddress((void**)&p_h, g_h);
    cudaGetSymbolAddress((void**)&p_t1, g_t1);
    cudaGetSymbolAddress((void**)&p_eidx, g_eidx);
    const int* src = p_eidx;
    const int* dst = p_eidx + E_EDGES;

    cudaFuncSetAttribute(edge_fused,
                         cudaFuncAttributeMaxDynamicSharedMemorySize, EL_SMEM_BYTES);

    int nsm = 148;
    cudaDeviceGetAttribute(&nsm, cudaDevAttrMultiProcessorCount, 0);

    const int T = 256;
    int gemm_blocks = (N_NODES + 127) / 128;
    int nhc_blocks = ((size_t)N_NODES * HC + T - 1) / T;

    detect_idx<<<1, 1>>>(ei_raw);
    conv_idx<<<(2 * E_EDGES + T - 1) / T, T>>>(ei_raw);

    pre_init<<<((size_t)N_NODES * LP + T - 1) / T, T>>>();
    loop_accum<<<(E_EDGES + T - 1) / T, T>>>(dst, ea);
    loop_fin<<<((size_t)N_NODES * EDIM + T - 1) / T, T>>>();

    // ---- layer 1 ----
    sgemm128x128<<<gemm_blocks, T>>>(x, c1_Wl, c1_bl, p_xl, N_NODES, 0);
    sgemm128x128<<<gemm_blocks, T>>>(x, c1_Wr, c1_br, p_xr, N_NODES, 0);
    layer_init<<<nhc_blocks, T>>>();
    edge_fused<<<nsm, 512, EL_SMEM_BYTES>>>(src, dst, ea, c1_We, c1_att);
    node_finalize<<<nhc_blocks, T>>>(c1_bias, p_h);

    // ---- layer 2 ----
    sgemm128x128<<<gemm_blocks, T>>>(p_h, c2_Wl, c2_bl, p_xl, N_NODES, 0);
    sgemm128x128<<<gemm_blocks, T>>>(p_h, c2_Wr, c2_br, p_xr, N_NODES, 0);
    layer_init<<<nhc_blocks, T>>>();
    edge_fused<<<nsm, 512, EL_SMEM_BYTES>>>(src, dst, ea, c2_We, c2_att);
    node_finalize<<<nhc_blocks, T>>>(c2_bias, p_h);

    // ---- MLP head ----
    sgemm128x128<<<gemm_blocks, T>>>(p_h, W1, b1, p_t1, N_NODES, 1);
    mlp_tail<<<(N_NODES + 15) / 16, 128>>>(W2, b2, W3, b3, out);
}

// round 7
// speedup vs baseline: 2.2964x; 1.5923x over previous
#include <cuda_runtime.h>
#include <cuda_bf16.h>
#include <math.h>
#include <stdint.h>

#define N_NODES 50000
#define E_EDGES 800000
#define N_ET    (E_EDGES + N_NODES)   // 850000 edges incl. self loops
#define EDIM    101
#define LP      104                   // padded loop_attr pitch
#define HC      128
#define NH      4

// ---- mma edge tile config ----
#define TILE_E  128
#define NTILES  ((N_ET + TILE_E - 1) / TILE_E)
#define NKS     7                     // 7 k-steps of 16 (K padded to 112)
#define PW      60                    // row pitch in bf16x2 words (120 bf16)
#define EEP     132                   // ee row pitch (floats)

// smem byte offsets
#define SM_ATT  0
#define SM_SS   512
#define SM_DS   1024
#define SM_EE   1536                       // 128*132*4 = 67584
#define SM_AHI  (SM_EE  + 128*EEP*4)       // 69120, 128*60*4 = 30720
#define SM_ALO  (SM_AHI + 128*PW*4)
#define SM_BHI  (SM_ALO + 128*PW*4)
#define SM_BLO  (SM_BHI + 128*PW*4)
#define SM_TOTAL (SM_BLO + 128*PW*4)       // 192000 bytes

// ------------------------------ scratch ------------------------------------
__device__ int   g_is64;
__device__ int   g_eidx[2 * E_EDGES];
__device__ float g_loop[(size_t)N_NODES * LP];
__device__ float g_cnt [N_NODES];
__device__ float g_xl  [(size_t)N_NODES * HC];
__device__ float g_xr  [(size_t)N_NODES * HC];
__device__ float g_h   [(size_t)N_NODES * HC];
__device__ float g_t1  [(size_t)N_NODES * HC];
__device__ float g_den [(size_t)N_NODES * NH];
__device__ float g_agg [(size_t)N_NODES * HC];

// ------------------------------ helpers ------------------------------------
__device__ __forceinline__ void redAdd4(float* p, float4 v) {
    asm volatile("red.global.add.v4.f32 [%0], {%1,%2,%3,%4};"
                 :: "l"(p), "f"(v.x), "f"(v.y), "f"(v.z), "f"(v.w) : "memory");
}

// packed fp32x2 (kept for node GEMMs; neutral perf, exact math)
__device__ __forceinline__ void fma2(unsigned long long& d,
                                     unsigned long long a, unsigned long long b) {
    asm("fma.rn.f32x2 %0, %1, %2, %0;" : "+l"(d) : "l"(a), "l"(b));
}
__device__ __forceinline__ unsigned long long dup2(float x) {
    unsigned long long r;
    asm("mov.b64 %0, {%1, %1};" : "=l"(r) : "r"(__float_as_uint(x)));
    return r;
}
__device__ __forceinline__ float2 unpk2(unsigned long long v) {
    unsigned int lo, hi;
    asm("mov.b64 {%0, %1}, %2;" : "=r"(lo), "=r"(hi) : "l"(v));
    return make_float2(__uint_as_float(lo), __uint_as_float(hi));
}

// bf16 hi/lo split of a float pair into packed b32 words (low 16 bits = v0)
__device__ __forceinline__ void split_bf16(float v0, float v1,
                                           uint32_t& hi, uint32_t& lo) {
    __nv_bfloat16 h0 = __float2bfloat16(v0), h1 = __float2bfloat16(v1);
    float r0 = v0 - __bfloat162float(h0);
    float r1 = v1 - __bfloat162float(h1);
    __nv_bfloat16 l0 = __float2bfloat16(r0), l1 = __float2bfloat16(r1);
    hi = (uint32_t)*reinterpret_cast<unsigned short*>(&h0)
       | ((uint32_t)*reinterpret_cast<unsigned short*>(&h1) << 16);
    lo = (uint32_t)*reinterpret_cast<unsigned short*>(&l0)
       | ((uint32_t)*reinterpret_cast<unsigned short*>(&l1) << 16);
}

// HMMA m16n8k16 bf16 (baseline PTX, sm_80+; no sm_103a-gated features)
__device__ __forceinline__ void mma_bf16(float* d,
                                         uint32_t a0, uint32_t a1, uint32_t a2, uint32_t a3,
                                         uint32_t b0, uint32_t b1) {
    asm volatile("mma.sync.aligned.m16n8k16.row.col.f32.bf16.bf16.f32 "
                 "{%0,%1,%2,%3}, {%4,%5,%6,%7}, {%8,%9}, {%0,%1,%2,%3};"
                 : "+f"(d[0]), "+f"(d[1]), "+f"(d[2]), "+f"(d[3])
                 : "r"(a0), "r"(a1), "r"(a2), "r"(a3), "r"(b0), "r"(b1));
}

// ------------------------------ index dtype hedge ---------------------------
__global__ void detect_idx(const void* ei) {
    const int* p = (const int*)ei;
    int all0 = 1;
    for (int i = 1; i < 64; i += 2) if (p[i] != 0) all0 = 0;
    g_is64 = all0;
}

__global__ void conv_idx(const void* ei) {
    int i = blockIdx.x * blockDim.x + threadIdx.x;
    if (i >= 2 * E_EDGES) return;
    int v;
    if (g_is64) v = (int)((const long long*)ei)[i];
    else        v = ((const int*)ei)[i];
    g_eidx[i] = v;
}

// ------------------------------ self-loop attr -----------------------------
__global__ void pre_init() {
    size_t i = (size_t)blockIdx.x * blockDim.x + threadIdx.x;
    if (i < (size_t)N_NODES * LP) g_loop[i] = 0.f;
    if (i < N_NODES) g_cnt[i] = 0.f;
}

__global__ void loop_accum(const int* __restrict__ dst, const float* __restrict__ ea) {
    int e = blockIdx.x * blockDim.x + threadIdx.x;
    if (e >= E_EDGES) return;
    int d = dst[e];
    float* out = g_loop + (size_t)d * LP;
    const float* a = ea + (size_t)e * EDIM;
#pragma unroll
    for (int k = 0; k < 100; k += 4) {
        float4 v = make_float4(a[k], a[k+1], a[k+2], a[k+3]);
        redAdd4(out + k, v);
    }
    atomicAdd(out + 100, a[100]);
    atomicAdd(&g_cnt[d], 1.0f);
}

__global__ void loop_fin() {
    size_t i = (size_t)blockIdx.x * blockDim.x + threadIdx.x;
    if (i >= (size_t)N_NODES * EDIM) return;
    int n = (int)(i / EDIM);
    int k = (int)(i - (size_t)n * EDIM);
    g_loop[(size_t)n * LP + k] *= 1.f / fmaxf(g_cnt[n], 1.f);
}

// ------------------------------ SGEMM (M x 128 = A[M,128] @ B[128,128]) ----
__global__ void sgemm128x128(const float* __restrict__ A, const float* __restrict__ B,
                             const float* __restrict__ bias, float* __restrict__ C,
                             int M, int relu) {
    __shared__ float As[8 * 132];
    __shared__ float Bs[8 * 128];
    int t = threadIdx.x;
    int m0 = blockIdx.x << 7;
    int la_m = t >> 1, la_k = (t & 1) << 2;
    int lb_k = t >> 5, lb_n = (t & 31) << 2;
    int tm = (t >> 4) << 3;
    int tn = (t & 15) << 2;

    unsigned long long acc[8][4];
#pragma unroll
    for (int i = 0; i < 8; i++)
#pragma unroll
        for (int j = 0; j < 4; j++) acc[i][j] = 0ull;

    for (int k0 = 0; k0 < 128; k0 += 8) {
        float4 av = make_float4(0.f, 0.f, 0.f, 0.f);
        if (m0 + la_m < M)
            av = *(const float4*)(A + (size_t)(m0 + la_m) * 128 + k0 + la_k);
        As[(la_k + 0) * 132 + la_m] = av.x;
        As[(la_k + 1) * 132 + la_m] = av.y;
        As[(la_k + 2) * 132 + la_m] = av.z;
        As[(la_k + 3) * 132 + la_m] = av.w;
        *(float4*)(Bs + lb_k * 128 + lb_n) =
            *(const float4*)(B + (size_t)(k0 + lb_k) * 128 + lb_n);
        __syncthreads();
#pragma unroll
        for (int k = 0; k < 8; k++) {
            float a[8];
            *(float4*)(a)     = *(const float4*)(As + k * 132 + tm);
            *(float4*)(a + 4) = *(const float4*)(As + k * 132 + tm + 4);
            ulonglong2 bA = *(const ulonglong2*)(Bs + k * 128 + tn);
            ulonglong2 bB = *(const ulonglong2*)(Bs + k * 128 + tn + 64);
            unsigned long long bp[4] = {bA.x, bA.y, bB.x, bB.y};
#pragma unroll
            for (int i = 0; i < 8; i++) {
                unsigned long long ad = dup2(a[i]);
#pragma unroll
                for (int j = 0; j < 4; j++) fma2(acc[i][j], ad, bp[j]);
            }
        }
        __syncthreads();
    }
#pragma unroll
    for (int i = 0; i < 8; i++) {
        int m = m0 + tm + i;
        if (m >= M) break;
        float o0[4], o1[4];
        float2 p0 = unpk2(acc[i][0]), p1 = unpk2(acc[i][1]);
        float2 p2 = unpk2(acc[i][2]), p3 = unpk2(acc[i][3]);
        o0[0] = p0.x + bias[tn + 0];  o0[1] = p0.y + bias[tn + 1];
        o0[2] = p1.x + bias[tn + 2];  o0[3] = p1.y + bias[tn + 3];
        o1[0] = p2.x + bias[tn + 64]; o1[1] = p2.y + bias[tn + 65];
        o1[2] = p3.x + bias[tn + 66]; o1[3] = p3.y + bias[tn + 67];
        if (relu) {
#pragma unroll
            for (int j = 0; j < 4; j++) {
                o0[j] = fmaxf(o0[j], 0.f);
                o1[j] = fmaxf(o1[j], 0.f);
            }
        }
        *(float4*)(C + (size_t)m * 128 + tn)      = *(float4*)(o0);
        *(float4*)(C + (size_t)m * 128 + tn + 64) = *(float4*)(o1);
    }
}

// ------------------------------ per-layer init ------------------------------
__global__ void layer_init() {
    size_t i = (size_t)blockIdx.x * blockDim.x + threadIdx.x;
    if (i < (size_t)N_NODES * HC) g_agg[i] = 0.f;
    if (i < (size_t)N_NODES * NH) g_den[i] = 0.f;
}

// ==== HMMA fused edge kernel: bf16 hi/lo 3-term ee GEMM + logit + exp + aggr
// 512 threads persistent. Warp w: edge block mb=w>>1 (16 edges), channel half
// w&1 (8 n-blocks of 8). ee staged in smem, then R6-style epilogue.
__global__ __launch_bounds__(512, 1)
void edge_mma(const int* __restrict__ src, const int* __restrict__ dst,
              const float* __restrict__ eattr,
              const float* __restrict__ We, const float* __restrict__ att) {
    extern __shared__ __align__(16) char sm[];
    float*    attS = (float*)(sm + SM_ATT);
    int*      ssS  = (int*)(sm + SM_SS);
    int*      dsS  = (int*)(sm + SM_DS);
    float*    ee   = (float*)(sm + SM_EE);
    float2*   ee2  = (float2*)(sm + SM_EE);
    uint32_t* Ahi  = (uint32_t*)(sm + SM_AHI);
    uint32_t* Alo  = (uint32_t*)(sm + SM_ALO);
    uint32_t* Bhi  = (uint32_t*)(sm + SM_BHI);
    uint32_t* Blo  = (uint32_t*)(sm + SM_BLO);

    int t = threadIdx.x;
    int lane = t & 31;
    int w = t >> 5;                 // 0..15
    int mb = w >> 1;                // edge block (16 edges)
    int half = w & 1;               // channel half (64 ch)
    int r0 = lane >> 2;             // fragment row
    int kp = lane & 3;              // fragment k-pair
    int head = lane >> 3;           // epilogue head

    // ---- stage B = We (k-major per channel row) hi/lo, once ----
    for (int i = t; i < 128 * 56; i += 512) {
        int c = i / 56, kq = i % 56;
        int k = kq * 2;
        float v0 = (k     < EDIM) ? We[(size_t)k * 128 + c]       : 0.f;
        float v1 = (k + 1 < EDIM) ? We[(size_t)(k + 1) * 128 + c] : 0.f;
        uint32_t h, l;
        split_bf16(v0, v1, h, l);
        Bhi[c * PW + kq] = h;
        Blo[c * PW + kq] = l;
    }
    if (t < 128) attS[t] = att[t];

    int e_st = t >> 2;              // staging: edge slot (0..127)
    int kq0  = (t & 3) * 14;        // staging: word range start

    for (int tile = blockIdx.x; tile < NTILES; tile += gridDim.x) {
        size_t e0 = (size_t)tile * TILE_E;
        __syncthreads();            // prev epilogue done; B/A safe to (re)write

        if (t < TILE_E) {
            size_t e = e0 + t;
            int s = 0, d = 0;
            if (e < (size_t)N_ET) {
                if (e < E_EDGES) { s = src[e]; d = dst[e]; }
                else             { s = d = (int)(e - E_EDGES); }
            }
            ssS[t] = s; dsS[t] = d;
        }

        // stage A tile hi/lo (4 threads per edge, 14 words = 28 k each)
        {
            size_t e = e0 + e_st;
            bool ok = (e < (size_t)N_ET);
            const float* bp = (e < E_EDGES) ? (eattr + e * EDIM)
                            : (g_loop + (ok ? (e - E_EDGES) : 0) * (size_t)LP);
            uint32_t* ah = Ahi + e_st * PW;
            uint32_t* al = Alo + e_st * PW;
#pragma unroll
            for (int i = 0; i < 14; i++) {
                int kq = kq0 + i;
                int k = kq * 2;
                float v0 = (ok && k     < EDIM) ? bp[k]     : 0.f;
                float v1 = (ok && k + 1 < EDIM) ? bp[k + 1] : 0.f;
                uint32_t h, l;
                split_bf16(v0, v1, h, l);
                ah[kq] = h;
                al[kq] = l;
            }
        }
        __syncthreads();

        // ---- HMMA: D = Ahi*Bhi + Ahi*Blo + Alo*Bhi ----
        float acc[8][4];
#pragma unroll
        for (int nb = 0; nb < 8; nb++)
#pragma unroll
            for (int j = 0; j < 4; j++) acc[nb][j] = 0.f;

        const uint32_t* Aw_h = Ahi + (mb << 4) * PW;
        const uint32_t* Aw_l = Alo + (mb << 4) * PW;
        const uint32_t* Bw_h = Bhi + (half << 6) * PW;
        const uint32_t* Bw_l = Blo + (half << 6) * PW;

#pragma unroll
        for (int ks = 0; ks < NKS; ks++) {
            int abase = r0 * PW + ks * 8 + kp;
            uint32_t ah0 = Aw_h[abase],           ah1 = Aw_h[abase + 8 * PW];
            uint32_t ah2 = Aw_h[abase + 4],       ah3 = Aw_h[abase + 8 * PW + 4];
            uint32_t al0 = Aw_l[abase],           al1 = Aw_l[abase + 8 * PW];
            uint32_t al2 = Aw_l[abase + 4],       al3 = Aw_l[abase + 8 * PW + 4];
#pragma unroll
            for (int nb = 0; nb < 8; nb++) {
                int bbase = ((nb << 3) + r0) * PW + ks * 8 + kp;
                uint32_t bh0 = Bw_h[bbase], bh1 = Bw_h[bbase + 4];
                uint32_t bl0 = Bw_l[bbase], bl1 = Bw_l[bbase + 4];
                mma_bf16(acc[nb], ah0, ah1, ah2, ah3, bh0, bh1);
                mma_bf16(acc[nb], ah0, ah1, ah2, ah3, bl0, bl1);
                mma_bf16(acc[nb], al0, al1, al2, al3, bh0, bh1);
            }
        }

        // store D fragments to ee smem
#pragma unroll
        for (int nb = 0; nb < 8; nb++) {
            int col2 = (half << 5) + (nb << 2) + kp;   // float2 units
            int row = (mb << 4) + r0;
            ee2[row * (EEP / 2) + col2]       = make_float2(acc[nb][0], acc[nb][1]);
            ee2[(row + 8) * (EEP / 2) + col2] = make_float2(acc[nb][2], acc[nb][3]);
        }
        __syncthreads();

        // ---- epilogue (R6 pattern): 8 edges per warp, lane = 4 channels ----
        float4 av = *(const float4*)(attS + (lane << 2));
#pragma unroll 1
        for (int i = 0; i < 8; i++) {
            int el = (w << 3) + i;
            size_t e = e0 + el;
            bool valid = (e < (size_t)N_ET);
            int s = valid ? ssS[el] : 0;
            int d = valid ? dsS[el] : 0;
            float4 eev = *(const float4*)(ee + el * EEP + (lane << 2));
            float4 xlv = *(const float4*)(g_xl + (size_t)s * HC + (lane << 2));
            float4 xrv = *(const float4*)(g_xr + (size_t)d * HC + (lane << 2));
            float z0 = eev.x + xlv.x + xrv.x;
            float z1 = eev.y + xlv.y + xrv.y;
            float z2 = eev.z + xlv.z + xrv.z;
            float z3 = eev.w + xlv.w + xrv.w;
            z0 = (z0 > 0.f) ? z0 : 0.2f * z0;
            z1 = (z1 > 0.f) ? z1 : 0.2f * z1;
            z2 = (z2 > 0.f) ? z2 : 0.2f * z2;
            z3 = (z3 > 0.f) ? z3 : 0.2f * z3;
            float part = z0 * av.x + z1 * av.y + z2 * av.z + z3 * av.w;
            part += __shfl_xor_sync(0xffffffffu, part, 1);
            part += __shfl_xor_sync(0xffffffffu, part, 2);
            part += __shfl_xor_sync(0xffffffffu, part, 4);
            float ex = __expf(part);
            if (valid) {
                if ((lane & 7) == 0)
                    atomicAdd(&g_den[(size_t)d * NH + head], ex);
                redAdd4(g_agg + (size_t)d * HC + (lane << 2),
                        make_float4(ex * xlv.x, ex * xlv.y,
                                    ex * xlv.z, ex * xlv.w));
            }
        }
    }
}

// --------------------- h = relu(agg/(den+eps) + bias) ----------------------
__global__ void node_finalize(const float* __restrict__ bias, float* __restrict__ out) {
    size_t i = (size_t)blockIdx.x * blockDim.x + threadIdx.x;
    if (i >= (size_t)N_NODES * HC) return;
    int n = (int)(i >> 7), c = (int)(i & 127);
    float den = g_den[(size_t)n * NH + (c >> 5)];
    float v = g_agg[i] / (den + 1e-16f) + bias[c];
    out[i] = fmaxf(v, 0.f);
}

// --------------------- MLP tail: relu(t1@W2+b2) @ W3 + b3 ------------------
__global__ void mlp_tail(const float* __restrict__ W2, const float* __restrict__ b2,
                         const float* __restrict__ W3, const float* __restrict__ b3,
                         float* __restrict__ out) {
    __shared__ float W2s[128 * 64];
    __shared__ float t1s[16 * 132];
    __shared__ float W3s[64];
    int t = threadIdx.x;
    int n0 = blockIdx.x * 16;
    for (int i = t; i < 128 * 64 / 4; i += 128)
        ((float4*)W2s)[i] = ((const float4*)W2)[i];
    if (t < 64) W3s[t] = W3[t];
    for (int i = t; i < 16 * 128; i += 128) {
        int ln = i >> 7, k = i & 127;
        int n = n0 + ln;
        t1s[ln * 132 + k] = (n < N_NODES) ? g_t1[(size_t)n * 128 + k] : 0.f;
    }
    __syncthreads();
    int ln = t >> 3, jg = t & 7;
    float acc[8] = {0.f, 0.f, 0.f, 0.f, 0.f, 0.f, 0.f, 0.f};
#pragma unroll 4
    for (int k = 0; k < 128; k++) {
        float a = t1s[ln * 132 + k];
        float4 w0 = *(const float4*)(W2s + k * 64 + jg * 8);
        float4 w1 = *(const float4*)(W2s + k * 64 + jg * 8 + 4);
        acc[0] += a * w0.x; acc[1] += a * w0.y; acc[2] += a * w0.z; acc[3] += a * w0.w;
        acc[4] += a * w1.x; acc[5] += a * w1.y; acc[6] += a * w1.z; acc[7] += a * w1.w;
    }
    float part = 0.f;
#pragma unroll
    for (int j = 0; j < 8; j++) {
        float t2 = fmaxf(acc[j] + b2[jg * 8 + j], 0.f);
        part += t2 * W3s[jg * 8 + j];
    }
    part += __shfl_down_sync(0xffffffffu, part, 4, 8);
    part += __shfl_down_sync(0xffffffffu, part, 2, 8);
    part += __shfl_down_sync(0xffffffffu, part, 1, 8);
    int n = n0 + ln;
    if (jg == 0 && n < N_NODES) out[n] = part + b3[0];
}

// ------------------------------ launch -------------------------------------
extern "C" void kernel_launch(void* const* d_in, const int* in_sizes, int n_in,
                              void* d_out, int out_size) {
    const float* x       = (const float*)d_in[0];
    const void*  ei_raw  = d_in[1];
    const float* ea      = (const float*)d_in[2];
    const float* c1_Wl   = (const float*)d_in[3];
    const float* c1_bl   = (const float*)d_in[4];
    const float* c1_Wr   = (const float*)d_in[5];
    const float* c1_br   = (const float*)d_in[6];
    const float* c1_We   = (const float*)d_in[7];
    const float* c1_att  = (const float*)d_in[8];
    const float* c1_bias = (const float*)d_in[9];
    const float* c2_Wl   = (const float*)d_in[10];
    const float* c2_bl   = (const float*)d_in[11];
    const float* c2_Wr   = (const float*)d_in[12];
    const float* c2_br   = (const float*)d_in[13];
    const float* c2_We   = (const float*)d_in[14];
    const float* c2_att  = (const float*)d_in[15];
    const float* c2_bias = (const float*)d_in[16];
    const float* W1      = (const float*)d_in[17];
    const float* b1      = (const float*)d_in[18];
    const float* W2      = (const float*)d_in[19];
    const float* b2      = (const float*)d_in[20];
    const float* W3      = (const float*)d_in[21];
    const float* b3      = (const float*)d_in[22];
    float* out = (float*)d_out;

    float *p_xl, *p_xr, *p_h, *p_t1;
    int *p_eidx;
    cudaGetSymbolAddress((void**)&p_xl, g_xl);
    cudaGetSymbolAddress((void**)&p_xr, g_xr);
    cudaGetSymbolAddress((void**)&p_h, g_h);
    cudaGetSymbolAddress((void**)&p_t1, g_t1);
    cudaGetSymbolAddress((void**)&p_eidx, g_eidx);
    const int* src = p_eidx;
    const int* dst = p_eidx + E_EDGES;

    cudaFuncSetAttribute(edge_mma,
                         cudaFuncAttributeMaxDynamicSharedMemorySize, SM_TOTAL);

    int nsm = 148;
    cudaDeviceGetAttribute(&nsm, cudaDevAttrMultiProcessorCount, 0);

    const int T = 256;
    int gemm_blocks = (N_NODES + 127) / 128;
    int nhc_blocks = ((size_t)N_NODES * HC + T - 1) / T;

    detect_idx<<<1, 1>>>(ei_raw);
    conv_idx<<<(2 * E_EDGES + T - 1) / T, T>>>(ei_raw);

    pre_init<<<((size_t)N_NODES * LP + T - 1) / T, T>>>();
    loop_accum<<<(E_EDGES + T - 1) / T, T>>>(dst, ea);
    loop_fin<<<((size_t)N_NODES * EDIM + T - 1) / T, T>>>();

    // ---- layer 1 ----
    sgemm128x128<<<gemm_blocks, T>>>(x, c1_Wl, c1_bl, p_xl, N_NODES, 0);
    sgemm128x128<<<gemm_blocks, T>>>(x, c1_Wr, c1_br, p_xr, N_NODES, 0);
    layer_init<<<nhc_blocks, T>>>();
    edge_mma<<<nsm, 512, SM_TOTAL>>>(src, dst, ea, c1_We, c1_att);
    node_finalize<<<nhc_blocks, T>>>(c1_bias, p_h);

    // ---- layer 2 ----
    sgemm128x128<<<gemm_blocks, T>>>(p_h, c2_Wl, c2_bl, p_xl, N_NODES, 0);
    sgemm128x128<<<gemm_blocks, T>>>(p_h, c2_Wr, c2_br, p_xr, N_NODES, 0);
    layer_init<<<nhc_blocks, T>>>();
    edge_mma<<<nsm, 512, SM_TOTAL>>>(src, dst, ea, c2_We, c2_att);
    node_finalize<<<nhc_blocks, T>>>(c2_bias, p_h);

    // ---- MLP head ----
    sgemm128x128<<<gemm_blocks, T>>>(p_h, W1, b1, p_t1, N_NODES, 1);
    mlp_tail<<<(N_NODES + 15) / 16, 128>>>(W2, b2, W3, b3, out);
}

// round 8
// speedup vs baseline: 2.6321x; 1.1462x over previous
#include <cuda_runtime.h>
#include <cuda_bf16.h>
#include <math.h>
#include <stdint.h>

#define N_NODES 50000
#define E_EDGES 800000
#define N_ET    (E_EDGES + N_NODES)   // 850000 edges incl. self loops
#define EDIM    101
#define LP      104                   // padded loop_attr pitch
#define HC      128
#define NH      4

// ---- mma edge tile config ----
#define TILE_E  128
#define NTILES  ((N_ET + TILE_E - 1) / TILE_E)
#define NKS     7                     // 7 k-steps of 16 (K padded to 112)
#define PW      60                    // row pitch in bf16x2 words (120 bf16)
#define EEP     132                   // ee row pitch (floats)

// smem byte offsets
#define SM_ATT  0
#define SM_SS   512
#define SM_DS   1024
#define SM_EE   1536                       // 128*132*4 = 67584
#define SM_AHI  (SM_EE  + 128*EEP*4)       // 69120, 128*60*4 = 30720
#define SM_ALO  (SM_AHI + 128*PW*4)
#define SM_BHI  (SM_ALO + 128*PW*4)
#define SM_BLO  (SM_BHI + 128*PW*4)
#define SM_TOTAL (SM_BLO + 128*PW*4)       // 192000 bytes

// ------------------------------ scratch ------------------------------------
__device__ int   g_is64;
__device__ int   g_eidx[2 * E_EDGES];
__device__ float g_loop[(size_t)N_NODES * LP];
__device__ float g_cnt [N_NODES];
__device__ float g_xl  [(size_t)N_NODES * HC];
__device__ float g_xr  [(size_t)N_NODES * HC];
__device__ float g_h   [(size_t)N_NODES * HC];
__device__ float g_t1  [(size_t)N_NODES * HC];
__device__ float g_den [(size_t)N_NODES * NH];
__device__ float g_agg [(size_t)N_NODES * HC];

// ------------------------------ helpers ------------------------------------
__device__ __forceinline__ void redAdd4(float* p, float4 v) {
    asm volatile("red.global.add.v4.f32 [%0], {%1,%2,%3,%4};"
                 :: "l"(p), "f"(v.x), "f"(v.y), "f"(v.z), "f"(v.w) : "memory");
}

// packed fp32x2 (node GEMMs; exact math)
__device__ __forceinline__ void fma2(unsigned long long& d,
                                     unsigned long long a, unsigned long long b) {
    asm("fma.rn.f32x2 %0, %1, %2, %0;" : "+l"(d) : "l"(a), "l"(b));
}
__device__ __forceinline__ unsigned long long dup2(float x) {
    unsigned long long r;
    asm("mov.b64 %0, {%1, %1};" : "=l"(r) : "r"(__float_as_uint(x)));
    return r;
}
__device__ __forceinline__ float2 unpk2(unsigned long long v) {
    unsigned int lo, hi;
    asm("mov.b64 {%0, %1}, %2;" : "=r"(lo), "=r"(hi) : "l"(v));
    return make_float2(__uint_as_float(lo), __uint_as_float(hi));
}

// truncation-based bf16 hi/lo split of a float pair (PRMT pack; residual 2^-16)
__device__ __forceinline__ void split_trunc(float v0, float v1,
                                            uint32_t& hi, uint32_t& lo) {
    uint32_t u0 = __float_as_uint(v0), u1 = __float_as_uint(v1);
    hi = __byte_perm(u0, u1, 0x7632);
    float r0 = v0 - __uint_as_float(u0 & 0xFFFF0000u);
    float r1 = v1 - __uint_as_float(u1 & 0xFFFF0000u);
    lo = __byte_perm(__float_as_uint(r0), __float_as_uint(r1), 0x7632);
}

// HMMA m16n8k16 bf16 (baseline PTX, sm_80+)
__device__ __forceinline__ void mma_bf16(float* d,
                                         uint32_t a0, uint32_t a1, uint32_t a2, uint32_t a3,
                                         uint32_t b0, uint32_t b1) {
    asm volatile("mma.sync.aligned.m16n8k16.row.col.f32.bf16.bf16.f32 "
                 "{%0,%1,%2,%3}, {%4,%5,%6,%7}, {%8,%9}, {%0,%1,%2,%3};"
                 : "+f"(d[0]), "+f"(d[1]), "+f"(d[2]), "+f"(d[3])
                 : "r"(a0), "r"(a1), "r"(a2), "r"(a3), "r"(b0), "r"(b1));
}

// ------------------------------ index dtype hedge ---------------------------
__global__ void detect_idx(const void* ei) {
    const int* p = (const int*)ei;
    int all0 = 1;
    for (int i = 1; i < 64; i += 2) if (p[i] != 0) all0 = 0;
    g_is64 = all0;
}

__global__ void conv_idx(const void* ei) {
    int i = blockIdx.x * blockDim.x + threadIdx.x;
    if (i >= 2 * E_EDGES) return;
    int v;
    if (g_is64) v = (int)((const long long*)ei)[i];
    else        v = ((const int*)ei)[i];
    g_eidx[i] = v;
}

// ------------------------------ self-loop attr -----------------------------
__global__ void pre_init() {
    size_t i = (size_t)blockIdx.x * blockDim.x + threadIdx.x;
    if (i < (size_t)N_NODES * LP) g_loop[i] = 0.f;
    if (i < N_NODES) g_cnt[i] = 0.f;
}

__global__ void loop_accum(const int* __restrict__ dst, const float* __restrict__ ea) {
    int e = blockIdx.x * blockDim.x + threadIdx.x;
    if (e >= E_EDGES) return;
    int d = dst[e];
    float* out = g_loop + (size_t)d * LP;
    const float* a = ea + (size_t)e * EDIM;
#pragma unroll
    for (int k = 0; k < 100; k += 4) {
        float4 v = make_float4(a[k], a[k+1], a[k+2], a[k+3]);
        redAdd4(out + k, v);
    }
    atomicAdd(out + 100, a[100]);
    atomicAdd(&g_cnt[d], 1.0f);
}

__global__ void loop_fin() {
    size_t i = (size_t)blockIdx.x * blockDim.x + threadIdx.x;
    if (i >= (size_t)N_NODES * EDIM) return;
    int n = (int)(i / EDIM);
    int k = (int)(i - (size_t)n * EDIM);
    g_loop[(size_t)n * LP + k] *= 1.f / fmaxf(g_cnt[n], 1.f);
}

// ------------------------------ SGEMM (M x 128 = A[M,128] @ B[128,128]) ----
__global__ void sgemm128x128(const float* __restrict__ A, const float* __restrict__ B,
                             const float* __restrict__ bias, float* __restrict__ C,
                             int M, int relu) {
    __shared__ float As[8 * 132];
    __shared__ float Bs[8 * 128];
    int t = threadIdx.x;
    int m0 = blockIdx.x << 7;
    int la_m = t >> 1, la_k = (t & 1) << 2;
    int lb_k = t >> 5, lb_n = (t & 31) << 2;
    int tm = (t >> 4) << 3;
    int tn = (t & 15) << 2;

    unsigned long long acc[8][4];
#pragma unroll
    for (int i = 0; i < 8; i++)
#pragma unroll
        for (int j = 0; j < 4; j++) acc[i][j] = 0ull;

    for (int k0 = 0; k0 < 128; k0 += 8) {
        float4 av = make_float4(0.f, 0.f, 0.f, 0.f);
        if (m0 + la_m < M)
            av = *(const float4*)(A + (size_t)(m0 + la_m) * 128 + k0 + la_k);
        As[(la_k + 0) * 132 + la_m] = av.x;
        As[(la_k + 1) * 132 + la_m] = av.y;
        As[(la_k + 2) * 132 + la_m] = av.z;
        As[(la_k + 3) * 132 + la_m] = av.w;
        *(float4*)(Bs + lb_k * 128 + lb_n) =
            *(const float4*)(B + (size_t)(k0 + lb_k) * 128 + lb_n);
        __syncthreads();
#pragma unroll
        for (int k = 0; k < 8; k++) {
            float a[8];
            *(float4*)(a)     = *(const float4*)(As + k * 132 + tm);
            *(float4*)(a + 4) = *(const float4*)(As + k * 132 + tm + 4);
            ulonglong2 bA = *(const ulonglong2*)(Bs + k * 128 + tn);
            ulonglong2 bB = *(const ulonglong2*)(Bs + k * 128 + tn + 64);
            unsigned long long bp[4] = {bA.x, bA.y, bB.x, bB.y};
#pragma unroll
            for (int i = 0; i < 8; i++) {
                unsigned long long ad = dup2(a[i]);
#pragma unroll
                for (int j = 0; j < 4; j++) fma2(acc[i][j], ad, bp[j]);
            }
        }
        __syncthreads();
    }
#pragma unroll
    for (int i = 0; i < 8; i++) {
        int m = m0 + tm + i;
        if (m >= M) break;
        float o0[4], o1[4];
        float2 p0 = unpk2(acc[i][0]), p1 = unpk2(acc[i][1]);
        float2 p2 = unpk2(acc[i][2]), p3 = unpk2(acc[i][3]);
        o0[0] = p0.x + bias[tn + 0];  o0[1] = p0.y + bias[tn + 1];
        o0[2] = p1.x + bias[tn + 2];  o0[3] = p1.y + bias[tn + 3];
        o1[0] = p2.x + bias[tn + 64]; o1[1] = p2.y + bias[tn + 65];
        o1[2] = p3.x + bias[tn + 66]; o1[3] = p3.y + bias[tn + 67];
        if (relu) {
#pragma unroll
            for (int j = 0; j < 4; j++) {
                o0[j] = fmaxf(o0[j], 0.f);
                o1[j] = fmaxf(o1[j], 0.f);
            }
        }
        *(float4*)(C + (size_t)m * 128 + tn)      = *(float4*)(o0);
        *(float4*)(C + (size_t)m * 128 + tn + 64) = *(float4*)(o1);
    }
}

// ------------------------------ per-layer init ------------------------------
__global__ void layer_init() {
    size_t i = (size_t)blockIdx.x * blockDim.x + threadIdx.x;
    if (i < (size_t)N_NODES * HC) g_agg[i] = 0.f;
    if (i < (size_t)N_NODES * NH) g_den[i] = 0.f;
}

// ==== HMMA fused edge kernel: pipelined staging + bf16 hi/lo 3-term GEMM +
//      batched-gather epilogue (logit + exp + aggregate) ====
__device__ __forceinline__ void prefetch_attrs(size_t e, int kbase, float* pf,
                                               const float* __restrict__ eattr) {
    bool ok = (e < (size_t)N_ET);
    const float* bp = (e < E_EDGES) ? (eattr + e * EDIM)
                    : (g_loop + (ok ? (e - E_EDGES) : 0) * (size_t)LP);
#pragma unroll
    for (int i = 0; i < 28; i++) {
        int k = kbase + i;
        pf[i] = (ok && k < EDIM) ? bp[k] : 0.f;
    }
}

__global__ __launch_bounds__(512, 1)
void edge_mma(const int* __restrict__ src, const int* __restrict__ dst,
              const float* __restrict__ eattr,
              const float* __restrict__ We, const float* __restrict__ att) {
    extern __shared__ __align__(16) char sm[];
    float*    attS = (float*)(sm + SM_ATT);
    int*      ssS  = (int*)(sm + SM_SS);
    int*      dsS  = (int*)(sm + SM_DS);
    float*    ee   = (float*)(sm + SM_EE);
    float2*   ee2  = (float2*)(sm + SM_EE);
    uint32_t* Ahi  = (uint32_t*)(sm + SM_AHI);
    uint32_t* Alo  = (uint32_t*)(sm + SM_ALO);
    uint32_t* Bhi  = (uint32_t*)(sm + SM_BHI);
    uint32_t* Blo  = (uint32_t*)(sm + SM_BLO);

    int t = threadIdx.x;
    int lane = t & 31;
    int w = t >> 5;                 // 0..15
    int mb = w >> 1;                // edge block (16 edges)
    int half = w & 1;               // channel half (64 ch)
    int r0 = lane >> 2;             // fragment row
    int kp = lane & 3;              // fragment k-pair
    int head = lane >> 3;           // epilogue head

    // ---- stage B = We (k-major per channel row) hi/lo, once ----
    for (int i = t; i < 128 * 56; i += 512) {
        int c = i / 56, kq = i % 56;
        int k = kq * 2;
        float v0 = (k     < EDIM) ? We[(size_t)k * 128 + c]       : 0.f;
        float v1 = (k + 1 < EDIM) ? We[(size_t)(k + 1) * 128 + c] : 0.f;
        uint32_t h, l;
        split_trunc(v0, v1, h, l);
        Bhi[c * PW + kq] = h;
        Blo[c * PW + kq] = l;
    }
    if (t < 128) attS[t] = att[t];

    int e_st = t >> 2;              // staging: edge slot (0..127)
    int kq0  = (t & 3) * 14;        // staging: word range start
    int kbase = kq0 * 2;

    // prefetch first tile's attrs into registers
    float pf[28];
    prefetch_attrs((size_t)blockIdx.x * TILE_E + e_st, kbase, pf, eattr);

    for (int tile = blockIdx.x; tile < NTILES; tile += gridDim.x) {
        size_t e0 = (size_t)tile * TILE_E;
        __syncthreads();            // prev tile reads of A/ee complete

        if (t < TILE_E) {
            size_t e = e0 + t;
            int s = 0, d = 0;
            if (e < (size_t)N_ET) {
                if (e < E_EDGES) { s = src[e]; d = dst[e]; }
                else             { s = d = (int)(e - E_EDGES); }
            }
            ssS[t] = s; dsS[t] = d;
        }

        // convert prefetched A attrs -> hi/lo smem
        {
            uint32_t* ah = Ahi + e_st * PW;
            uint32_t* al = Alo + e_st * PW;
#pragma unroll
            for (int i = 0; i < 14; i++) {
                uint32_t h, l;
                split_trunc(pf[2*i], pf[2*i + 1], h, l);
                ah[kq0 + i] = h;
                al[kq0 + i] = l;
            }
        }
        // issue next tile's prefetch (lands during MMA/epilogue)
        {
            int ntile = tile + gridDim.x;
            if (ntile < NTILES)
                prefetch_attrs((size_t)ntile * TILE_E + e_st, kbase, pf, eattr);
        }
        __syncthreads();

        // ---- HMMA: D = Ahi*Bhi + Ahi*Blo + Alo*Bhi ----
        float acc[8][4];
#pragma unroll
        for (int nb = 0; nb < 8; nb++)
#pragma unroll
            for (int j = 0; j < 4; j++) acc[nb][j] = 0.f;

        const uint32_t* Aw_h = Ahi + (mb << 4) * PW;
        const uint32_t* Aw_l = Alo + (mb << 4) * PW;
        const uint32_t* Bw_h = Bhi + (half << 6) * PW;
        const uint32_t* Bw_l = Blo + (half << 6) * PW;

#pragma unroll
        for (int ks = 0; ks < NKS; ks++) {
            int abase = r0 * PW + ks * 8 + kp;
            uint32_t ah0 = Aw_h[abase],     ah1 = Aw_h[abase + 8 * PW];
            uint32_t ah2 = Aw_h[abase + 4], ah3 = Aw_h[abase + 8 * PW + 4];
            uint32_t al0 = Aw_l[abase],     al1 = Aw_l[abase + 8 * PW];
            uint32_t al2 = Aw_l[abase + 4], al3 = Aw_l[abase + 8 * PW + 4];
#pragma unroll
            for (int nb = 0; nb < 8; nb++) {
                int bbase = ((nb << 3) + r0) * PW + ks * 8 + kp;
                uint32_t bh0 = Bw_h[bbase], bh1 = Bw_h[bbase + 4];
                uint32_t bl0 = Bw_l[bbase], bl1 = Bw_l[bbase + 4];
                mma_bf16(acc[nb], ah0, ah1, ah2, ah3, bh0, bh1);
                mma_bf16(acc[nb], ah0, ah1, ah2, ah3, bl0, bl1);
                mma_bf16(acc[nb], al0, al1, al2, al3, bh0, bh1);
            }
        }

        // store D fragments to ee smem
#pragma unroll
        for (int nb = 0; nb < 8; nb++) {
            int col2 = (half << 5) + (nb << 2) + kp;   // float2 units
            int row = (mb << 4) + r0;
            ee2[row * (EEP / 2) + col2]       = make_float2(acc[nb][0], acc[nb][1]);
            ee2[(row + 8) * (EEP / 2) + col2] = make_float2(acc[nb][2], acc[nb][3]);
        }
        __syncthreads();

        // ---- epilogue: 8 edges per warp, in 2 batches of 4 (gathers overlap)
        float4 av = *(const float4*)(attS + (lane << 2));
#pragma unroll
        for (int g = 0; g < 2; g++) {
            float4 xlv[4], xrv[4];
            int dd[4];
            bool vv[4];
#pragma unroll
            for (int i = 0; i < 4; i++) {
                int el = (w << 3) + (g << 2) + i;
                size_t e = e0 + el;
                bool valid = (e < (size_t)N_ET);
                int s = valid ? ssS[el] : 0;
                int d = valid ? dsS[el] : 0;
                vv[i] = valid; dd[i] = d;
                xlv[i] = *(const float4*)(g_xl + (size_t)s * HC + (lane << 2));
                xrv[i] = *(const float4*)(g_xr + (size_t)d * HC + (lane << 2));
            }
#pragma unroll
            for (int i = 0; i < 4; i++) {
                int el = (w << 3) + (g << 2) + i;
                float4 eev = *(const float4*)(ee + el * EEP + (lane << 2));
                float z0 = eev.x + xlv[i].x + xrv[i].x;
                float z1 = eev.y + xlv[i].y + xrv[i].y;
                float z2 = eev.z + xlv[i].z + xrv[i].z;
                float z3 = eev.w + xlv[i].w + xrv[i].w;
                z0 = (z0 > 0.f) ? z0 : 0.2f * z0;
                z1 = (z1 > 0.f) ? z1 : 0.2f * z1;
                z2 = (z2 > 0.f) ? z2 : 0.2f * z2;
                z3 = (z3 > 0.f) ? z3 : 0.2f * z3;
                float part = z0 * av.x + z1 * av.y + z2 * av.z + z3 * av.w;
                part += __shfl_xor_sync(0xffffffffu, part, 1);
                part += __shfl_xor_sync(0xffffffffu, part, 2);
                part += __shfl_xor_sync(0xffffffffu, part, 4);
                float ex = __expf(part);
                if (vv[i]) {
                    if ((lane & 7) == 0)
                        atomicAdd(&g_den[(size_t)dd[i] * NH + head], ex);
                    redAdd4(g_agg + (size_t)dd[i] * HC + (lane << 2),
                            make_float4(ex * xlv[i].x, ex * xlv[i].y,
                                        ex * xlv[i].z, ex * xlv[i].w));
                }
            }
        }
    }
}

// --------------------- h = relu(agg/(den+eps) + bias) ----------------------
__global__ void node_finalize(const float* __restrict__ bias, float* __restrict__ out) {
    size_t i = (size_t)blockIdx.x * blockDim.x + threadIdx.x;
    if (i >= (size_t)N_NODES * HC) return;
    int n = (int)(i >> 7), c = (int)(i & 127);
    float den = g_den[(size_t)n * NH + (c >> 5)];
    float v = g_agg[i] / (den + 1e-16f) + bias[c];
    out[i] = fmaxf(v, 0.f);
}

// --------------------- MLP tail: relu(t1@W2+b2) @ W3 + b3 ------------------
__global__ void mlp_tail(const float* __restrict__ W2, const float* __restrict__ b2,
                         const float* __restrict__ W3, const float* __restrict__ b3,
                         float* __restrict__ out) {
    __shared__ float W2s[128 * 64];
    __shared__ float t1s[16 * 132];
    __shared__ float W3s[64];
    int t = threadIdx.x;
    int n0 = blockIdx.x * 16;
    for (int i = t; i < 128 * 64 / 4; i += 128)
        ((float4*)W2s)[i] = ((const float4*)W2)[i];
    if (t < 64) W3s[t] = W3[t];
    for (int i = t; i < 16 * 128; i += 128) {
        int ln = i >> 7, k = i & 127;
        int n = n0 + ln;
        t1s[ln * 132 + k] = (n < N_NODES) ? g_t1[(size_t)n * 128 + k] : 0.f;
    }
    __syncthreads();
    int ln = t >> 3, jg = t & 7;
    float acc[8] = {0.f, 0.f, 0.f, 0.f, 0.f, 0.f, 0.f, 0.f};
#pragma unroll 4
    for (int k = 0; k < 128; k++) {
        float a = t1s[ln * 132 + k];
        float4 w0 = *(const float4*)(W2s + k * 64 + jg * 8);
        float4 w1 = *(const float4*)(W2s + k * 64 + jg * 8 + 4);
        acc[0] += a * w0.x; acc[1] += a * w0.y; acc[2] += a * w0.z; acc[3] += a * w0.w;
        acc[4] += a * w1.x; acc[5] += a * w1.y; acc[6] += a * w1.z; acc[7] += a * w1.w;
    }
    float part = 0.f;
#pragma unroll
    for (int j = 0; j < 8; j++) {
        float t2 = fmaxf(acc[j] + b2[jg * 8 + j], 0.f);
        part += t2 * W3s[jg * 8 + j];
    }
    part += __shfl_down_sync(0xffffffffu, part, 4, 8);
    part += __shfl_down_sync(0xffffffffu, part, 2, 8);
    part += __shfl_down_sync(0xffffffffu, part, 1, 8);
    int n = n0 + ln;
    if (jg == 0 && n < N_NODES) out[n] = part + b3[0];
}

// ------------------------------ launch -------------------------------------
extern "C" void kernel_launch(void* const* d_in, const int* in_sizes, int n_in,
                              void* d_out, int out_size) {
    const float* x       = (const float*)d_in[0];
    const void*  ei_raw  = d_in[1];
    const float* ea      = (const float*)d_in[2];
    const float* c1_Wl   = (const float*)d_in[3];
    const float* c1_bl   = (const float*)d_in[4];
    const float* c1_Wr   = (const float*)d_in[5];
    const float* c1_br   = (const float*)d_in[6];
    const float* c1_We   = (const float*)d_in[7];
    const float* c1_att  = (const float*)d_in[8];
    const float* c1_bias = (const float*)d_in[9];
    const float* c2_Wl   = (const float*)d_in[10];
    const float* c2_bl   = (const float*)d_in[11];
    const float* c2_Wr   = (const float*)d_in[12];
    const float* c2_br   = (const float*)d_in[13];
    const float* c2_We   = (const float*)d_in[14];
    const float* c2_att  = (const float*)d_in[15];
    const float* c2_bias = (const float*)d_in[16];
    const float* W1      = (const float*)d_in[17];
    const float* b1      = (const float*)d_in[18];
    const float* W2      = (const float*)d_in[19];
    const float* b2      = (const float*)d_in[20];
    const float* W3      = (const float*)d_in[21];
    const float* b3      = (const float*)d_in[22];
    float* out = (float*)d_out;

    float *p_xl, *p_xr, *p_h, *p_t1;
    int *p_eidx;
    cudaGetSymbolAddress((void**)&p_xl, g_xl);
    cudaGetSymbolAddress((void**)&p_xr, g_xr);
    cudaGetSymbolAddress((void**)&p_h, g_h);
    cudaGetSymbolAddress((void**)&p_t1, g_t1);
    cudaGetSymbolAddress((void**)&p_eidx, g_eidx);
    const int* src = p_eidx;
    const int* dst = p_eidx + E_EDGES;

    cudaFuncSetAttribute(edge_mma,
                         cudaFuncAttributeMaxDynamicSharedMemorySize, SM_TOTAL);

    int nsm = 148;
    cudaDeviceGetAttribute(&nsm, cudaDevAttrMultiProcessorCount, 0);

    const int T = 256;
    int gemm_blocks = (N_NODES + 127) / 128;
    int nhc_blocks = ((size_t)N_NODES * HC + T - 1) / T;

    detect_idx<<<1, 1>>>(ei_raw);
    conv_idx<<<(2 * E_EDGES + T - 1) / T, T>>>(ei_raw);

    pre_init<<<((size_t)N_NODES * LP + T - 1) / T, T>>>();
    loop_accum<<<(E_EDGES + T - 1) / T, T>>>(dst, ea);
    loop_fin<<<((size_t)N_NODES * EDIM + T - 1) / T, T>>>();

    // ---- layer 1 ----
    sgemm128x128<<<gemm_blocks, T>>>(x, c1_Wl, c1_bl, p_xl, N_NODES, 0);
    sgemm128x128<<<gemm_blocks, T>>>(x, c1_Wr, c1_br, p_xr, N_NODES, 0);
    layer_init<<<nhc_blocks, T>>>();
    edge_mma<<<nsm, 512, SM_TOTAL>>>(src, dst, ea, c1_We, c1_att);
    node_finalize<<<nhc_blocks, T>>>(c1_bias, p_h);

    // ---- layer 2 ----
    sgemm128x128<<<gemm_blocks, T>>>(p_h, c2_Wl, c2_bl, p_xl, N_NODES, 0);
    sgemm128x128<<<gemm_blocks, T>>>(p_h, c2_Wr, c2_br, p_xr, N_NODES, 0);
    layer_init<<<nhc_blocks, T>>>();
    edge_mma<<<nsm, 512, SM_TOTAL>>>(src, dst, ea, c2_We, c2_att);
    node_finalize<<<nhc_blocks, T>>>(c2_bias, p_h);

    // ---- MLP head ----
    sgemm128x128<<<gemm_blocks, T>>>(p_h, W1, b1, p_t1, N_NODES, 1);
    mlp_tail<<<(N_NODES + 15) / 16, 128>>>(W2, b2, W3, b3, out);
}